// round 8
// baseline (speedup 1.0000x reference)
#include <cuda_runtime.h>
#include <cuda_bf16.h>
#include <cstdint>
#include <math.h>

#define BB  64
#define NV  2048
#define NQ  512
#define HH  256
#define HA  128

typedef __nv_bfloat16 bf16;

// ---------------- scratch (device globals) ---------------------------------
__device__ bf16 g_vhi[(size_t)BB*NV*HH], g_vlo[(size_t)BB*NV*HH];
__device__ bf16 g_qhi[(size_t)BB*NQ*HH], g_qlo[(size_t)BB*NQ*HH];
__device__ bf16 g_Wahi[HH*HH],  g_Walo[HH*HH];
__device__ bf16 g_Wvhi[HA*HH],  g_Wvlo[HA*HH];
__device__ bf16 g_Wqhi[HA*HH],  g_Wqlo[HA*HH];
__device__ bf16 g_vahi[(size_t)BB*NV*HH], g_valo[(size_t)BB*NV*HH];
__device__ float g_pv[(size_t)BB*NV*HA];
__device__ bf16 g_pvThi[(size_t)BB*HA*NV], g_pvTlo[(size_t)BB*HA*NV];
__device__ float g_pq[(size_t)BB*NQ*HA];
__device__ bf16 g_pqThi[(size_t)BB*HA*NQ], g_pqTlo[(size_t)BB*HA*NQ];
__device__ bf16 g_affhi[(size_t)BB*NQ*NV], g_afflo[(size_t)BB*NQ*NV];
__device__ bf16 g_afThi[(size_t)BB*NV*NQ], g_afTlo[(size_t)BB*NV*NQ];
__device__ float g_lv[BB*NV], g_lq[BB*NQ];

#define TILE_B   10240               // 128 rows * 80B
#define BUF_B    (4 * TILE_B)        // Ahi, Alo, Bhi, Blo
#define DYNSMEM  (2 * BUF_B)         // 81920 (double buffer)
#define PLANE_B  33280               // 128*130*2 bounce plane

// ======================= low-level helpers =================================
__device__ __forceinline__ uint32_t smem_u32(const void* p) {
    uint32_t a;
    asm("{ .reg .u64 t; cvta.to.shared.u64 t, %1; cvt.u32.u64 %0, t; }"
        : "=r"(a) : "l"(p));
    return a;
}
__device__ __forceinline__ void ldsm4(uint32_t* r, uint32_t a) {
    asm volatile("ldmatrix.sync.aligned.m8n8.x4.shared.b16 {%0,%1,%2,%3}, [%4];"
                 : "=r"(r[0]), "=r"(r[1]), "=r"(r[2]), "=r"(r[3]) : "r"(a));
}
__device__ __forceinline__ void mma_bf16(float* c, const uint32_t* a,
                                         const uint32_t* b) {
    asm volatile(
        "mma.sync.aligned.m16n8k16.row.col.f32.bf16.bf16.f32 "
        "{%0,%1,%2,%3}, {%4,%5,%6,%7}, {%8,%9}, {%0,%1,%2,%3};"
        : "+f"(c[0]), "+f"(c[1]), "+f"(c[2]), "+f"(c[3])
        : "r"(a[0]), "r"(a[1]), "r"(a[2]), "r"(a[3]), "r"(b[0]), "r"(b[1]));
}
__device__ __forceinline__ void cvt_split2(float x, float y, uint32_t& hi, uint32_t& lo) {
    uint32_t h;
    asm("cvt.rn.bf16x2.f32 %0, %1, %2;" : "=r"(h) : "f"(y), "f"(x));
    float hx = __uint_as_float(h << 16);
    float hy = __uint_as_float(h & 0xFFFF0000u);
    uint32_t l;
    asm("cvt.rn.bf16x2.f32 %0, %1, %2;" : "=r"(l) : "f"(y - hy), "f"(x - hx));
    hi = h; lo = l;
}
__device__ __forceinline__ float tanh_fast(float x) {
    float e = __expf(2.0f * x);
    return 1.0f - __fdividef(2.0f, e + 1.0f);
}

// cp.async stage: 4 tiles (Ahi,Alo,Bhi,Blo), each 128 rows x 64B -> 80B rows
__device__ __forceinline__ void stage_async(uint32_t buf,
        const bf16* __restrict__ Ahi, const bf16* __restrict__ Alo,
        const bf16* __restrict__ Bhi, const bf16* __restrict__ Blo,
        int lda, int ldb, int k0) {
    const int sel = threadIdx.x >> 6;
    const bf16* src = (sel == 0) ? Ahi : (sel == 1) ? Alo : (sel == 2) ? Bhi : Blo;
    const int ld = (sel < 2) ? lda : ldb;
    const int t = threadIdx.x & 63;
    const uint32_t dst = buf + sel * TILE_B;
#pragma unroll
    for (int c = 0; c < 8; ++c) {
        const int lin = c * 64 + t;
        const int row = lin >> 2, qt = lin & 3;
        asm volatile("cp.async.cg.shared.global [%0], [%1], 16;"
            :: "r"(dst + row * 80 + qt * 16),
               "l"((const char*)(src + (long)row * ld + k0) + qt * 16));
    }
}

// write a 128x128 bf16 smem plane (stride 130) to gmem, optional transpose
__device__ __forceinline__ void plane_out(const uint16_t* __restrict__ sm,
                                          bf16* __restrict__ dst,
                                          long row0, long col0, long ld, int tr) {
    const int tid = threadIdx.x;
#pragma unroll
    for (int cI = 0; cI < 8; ++cI) {
        const int g = cI * 256 + tid;
        const int r = g >> 4, ch = g & 15;
        uint16_t e[8];
#pragma unroll
        for (int i = 0; i < 8; ++i)
            e[i] = tr ? sm[(ch * 8 + i) * 130 + r] : sm[r * 130 + ch * 8 + i];
        uint4 w;
        w.x = e[0] | ((uint32_t)e[1] << 16);
        w.y = e[2] | ((uint32_t)e[3] << 16);
        w.z = e[4] | ((uint32_t)e[5] << 16);
        w.w = e[6] | ((uint32_t)e[7] << 16);
        *(uint4*)(dst + (row0 + r) * ld + col0 + ch * 8) = w;
    }
}

// ============================================================================
// split fp32 array -> bf16 hi/lo planes
// ============================================================================
__global__ __launch_bounds__(256)
void split_kernel(const float* __restrict__ x, bf16* __restrict__ hi,
                  bf16* __restrict__ lo, long n)
{
    const long i = ((long)blockIdx.x * 256 + threadIdx.x) * 4;
    if (i >= n) return;
    const float4 v = *(const float4*)(x + i);
    uint32_t h0, l0, h1, l1;
    cvt_split2(v.x, v.y, h0, l0);
    cvt_split2(v.z, v.w, h1, l1);
    *(uint2*)((uint32_t*)hi + (i >> 1)) = make_uint2(h0, h1);
    *(uint2*)((uint32_t*)lo + (i >> 1)) = make_uint2(l0, l1);
}

// ============================================================================
// mma2: C[128-tile] = A @ B^T, bf16 hi/lo pre-split operands, 3-MMA split.
// 128x128x32 CTA tile, 8 warps (32x64), cp.async double buffer, 2 CTA/SM.
// Inner loop: B fragments loaded per 16-col group; 12 MMAs per group ordered
// pass-major so accumulator reuse distance is 4 (breaks HMMA RAW chains).
// MODE 0: Chi/Clo = split(acc + bias)                       [va]
// MODE 1: Cf = acc + bias (fp32); CThi/lo = transposed split [pv,pq]
// MODE 2: Chi/lo = split(tanh(acc)); CThi/lo transposed      [aff]
// MODE 3: logits[m] = Wh . tanh(PAdd[m] + acc[m]) + bh       [hidden]
// ============================================================================
template<int MODE>
__global__ __launch_bounds__(256, 2)
void mma2(const bf16* __restrict__ Ahi, const bf16* __restrict__ Alo,
          const bf16* __restrict__ Bhi, const bf16* __restrict__ Blo,
          const float* __restrict__ bias,
          bf16* __restrict__ Chi, bf16* __restrict__ Clo,
          bf16* __restrict__ CThi, bf16* __restrict__ CTlo,
          float* __restrict__ Cf,
          const float* __restrict__ PAdd, const float* __restrict__ Wh,
          const float* __restrict__ bh, float* __restrict__ logits,
          int K, int lda, int ldb, int ldC, int ldCT, int rpb,
          long sA, long sB, long sOC, long sOCT, long sPAdd, int sLog)
{
    extern __shared__ __align__(16) unsigned char smem_[];
    __shared__ float sPart[2][128];

    const int z = blockIdx.z;
    Ahi += z * sA;  Alo += z * sA;  Bhi += z * sB;  Blo += z * sB;
    if (MODE == 2) { Chi += z * sOC; Clo += z * sOC; CThi += z * sOCT; CTlo += z * sOCT; }
    if (MODE == 3) { PAdd += z * sPAdd; logits += (long)z * sLog; }

    const long m0 = (long)(MODE == 3 ? blockIdx.x : blockIdx.y) * 128;
    const long n0 = (MODE == 3) ? 0 : (long)blockIdx.x * 128;
    Ahi += m0 * lda;  Alo += m0 * lda;  Bhi += n0 * ldb;  Blo += n0 * ldb;

    const uint32_t sb0 = smem_u32(smem_);
    const int tid = threadIdx.x;
    const int l = tid & 31, wid = tid >> 5;
    const int wm = wid & 3, wn = wid >> 2;

    const int sub = l >> 3, lr = l & 7;
    const uint32_t aRow = wm * 32 + ((sub & 1) << 3) + lr;
    const uint32_t aK   = (uint32_t)((sub >> 1) << 3);
    const uint32_t bRow = ((sub & 2) << 2) + lr;
    const uint32_t bK   = (uint32_t)((sub & 1) << 3);

    float acc[2][8][4] = {};

    stage_async(sb0, Ahi, Alo, Bhi, Blo, lda, ldb, 0);
    asm volatile("cp.async.commit_group;" ::: "memory");

    const int nchunk = K >> 5;
    for (int ch = 0; ch < nchunk; ++ch) {
        if (ch + 1 < nchunk) {
            stage_async(sb0 + ((ch + 1) & 1) * BUF_B, Ahi, Alo, Bhi, Blo,
                        lda, ldb, (ch + 1) * 32);
            asm volatile("cp.async.commit_group;" ::: "memory");
            asm volatile("cp.async.wait_group 1;" ::: "memory");
        } else {
            asm volatile("cp.async.wait_group 0;" ::: "memory");
        }
        __syncthreads();

        const uint32_t cur = sb0 + (ch & 1) * BUF_B;
        const uint32_t sAhi = cur,              sAlo = cur + TILE_B;
        const uint32_t sBhi = cur + 2 * TILE_B, sBlo = cur + 3 * TILE_B;

#pragma unroll
        for (int kt = 0; kt < 32; kt += 16) {
            uint32_t Ah[2][4], Al[2][4];
            const uint32_t ak = (kt + aK) * 2;
#pragma unroll
            for (int mt = 0; mt < 2; ++mt) {
                const uint32_t ra = (aRow + mt * 16) * 80 + ak;
                ldsm4(Ah[mt], sAhi + ra);
                ldsm4(Al[mt], sAlo + ra);
            }
            const uint32_t bk = (kt + bK) * 2;
#pragma unroll
            for (int g = 0; g < 4; ++g) {
                uint32_t Bh[4], Bl[4];
                const uint32_t rb = (wn * 64 + g * 16 + bRow) * 80 + bk;
                ldsm4(Bh, sBhi + rb);
                ldsm4(Bl, sBlo + rb);
                // pass-major: accumulator reuse distance = 4 independent MMAs
                mma_bf16(acc[0][2*g],   Ah[0], &Bh[0]);
                mma_bf16(acc[0][2*g+1], Ah[0], &Bh[2]);
                mma_bf16(acc[1][2*g],   Ah[1], &Bh[0]);
                mma_bf16(acc[1][2*g+1], Ah[1], &Bh[2]);
                mma_bf16(acc[0][2*g],   Ah[0], &Bl[0]);
                mma_bf16(acc[0][2*g+1], Ah[0], &Bl[2]);
                mma_bf16(acc[1][2*g],   Ah[1], &Bl[0]);
                mma_bf16(acc[1][2*g+1], Ah[1], &Bl[2]);
                mma_bf16(acc[0][2*g],   Al[0], &Bh[0]);
                mma_bf16(acc[0][2*g+1], Al[0], &Bh[2]);
                mma_bf16(acc[1][2*g],   Al[1], &Bh[0]);
                mma_bf16(acc[1][2*g+1], Al[1], &Bh[2]);
            }
        }
        __syncthreads();
    }

    // ---------------- epilogues ----------------
    if (MODE == 0) {
#pragma unroll
        for (int mt = 0; mt < 2; ++mt) {
            const long r0 = m0 + wm * 32 + mt * 16 + (l >> 2);
#pragma unroll
            for (int nt = 0; nt < 8; ++nt) {
                const long col = n0 + wn * 64 + nt * 8 + 2 * (l & 3);
                const float2 b2 = *(const float2*)&bias[col];
                uint32_t h, lo;
                cvt_split2(acc[mt][nt][0] + b2.x, acc[mt][nt][1] + b2.y, h, lo);
                ((uint32_t*)Chi)[(r0 * (long)ldC + col) >> 1] = h;
                ((uint32_t*)Clo)[(r0 * (long)ldC + col) >> 1] = lo;
                cvt_split2(acc[mt][nt][2] + b2.x, acc[mt][nt][3] + b2.y, h, lo);
                ((uint32_t*)Chi)[((r0 + 8) * (long)ldC + col) >> 1] = h;
                ((uint32_t*)Clo)[((r0 + 8) * (long)ldC + col) >> 1] = lo;
            }
        }
    } else if (MODE == 1 || MODE == 2) {
        uint32_t* pHi = (uint32_t*)smem_;
        uint32_t* pLo = (uint32_t*)(smem_ + PLANE_B);
#pragma unroll
        for (int mt = 0; mt < 2; ++mt) {
            const int rl = wm * 32 + mt * 16 + (l >> 2);
#pragma unroll
            for (int nt = 0; nt < 8; ++nt) {
                const int c = wn * 64 + nt * 8 + 2 * (l & 3);
                float v0 = acc[mt][nt][0], v1 = acc[mt][nt][1];
                float v2 = acc[mt][nt][2], v3 = acc[mt][nt][3];
                if (MODE == 1) {
                    const float2 b2 = *(const float2*)&bias[n0 + c];
                    v0 += b2.x; v1 += b2.y; v2 += b2.x; v3 += b2.y;
                    const long r0 = m0 + rl;
                    *(float2*)&Cf[r0 * (long)ldC + n0 + c]       = make_float2(v0, v1);
                    *(float2*)&Cf[(r0 + 8) * (long)ldC + n0 + c] = make_float2(v2, v3);
                } else {
                    v0 = tanh_fast(v0); v1 = tanh_fast(v1);
                    v2 = tanh_fast(v2); v3 = tanh_fast(v3);
                }
                uint32_t h, lo;
                cvt_split2(v0, v1, h, lo);
                pHi[(rl * 130 + c) >> 1] = h;
                pLo[(rl * 130 + c) >> 1] = lo;
                cvt_split2(v2, v3, h, lo);
                pHi[((rl + 8) * 130 + c) >> 1] = h;
                pLo[((rl + 8) * 130 + c) >> 1] = lo;
            }
        }
        __syncthreads();
        const uint16_t* smHi = (const uint16_t*)smem_;
        const uint16_t* smLo = (const uint16_t*)(smem_ + PLANE_B);
        if (MODE == 1) {
            const long b = m0 / rpb, nIn = m0 - b * rpb;
            plane_out(smHi, CThi, b * HA, nIn, ldCT, 1);
            plane_out(smLo, CTlo, b * HA, nIn, ldCT, 1);
        } else {
            plane_out(smHi, Chi,  m0, n0, ldC, 0);
            plane_out(smLo, Clo,  m0, n0, ldC, 0);
            plane_out(smHi, CThi, n0, m0, ldCT, 1);
            plane_out(smLo, CTlo, n0, m0, ldCT, 1);
        }
    } else {  // MODE 3
        float2 whr[8];
#pragma unroll
        for (int nt = 0; nt < 8; ++nt)
            whr[nt] = *(const float2*)&Wh[wn * 64 + nt * 8 + 2 * (l & 3)];
#pragma unroll
        for (int mt = 0; mt < 2; ++mt) {
            const int rr = wm * 32 + mt * 16 + (l >> 2);
            float s0 = 0.f, s1 = 0.f;
#pragma unroll
            for (int nt = 0; nt < 8; ++nt) {
                const int col = wn * 64 + nt * 8 + 2 * (l & 3);
                const float2 w = whr[nt];
                const float2 p0 = *(const float2*)&PAdd[(m0 + rr) * (long)HA + col];
                const float2 p1 = *(const float2*)&PAdd[(m0 + rr + 8) * (long)HA + col];
                s0 += w.x * tanh_fast(p0.x + acc[mt][nt][0])
                    + w.y * tanh_fast(p0.y + acc[mt][nt][1]);
                s1 += w.x * tanh_fast(p1.x + acc[mt][nt][2])
                    + w.y * tanh_fast(p1.y + acc[mt][nt][3]);
            }
            s0 += __shfl_xor_sync(0xffffffffu, s0, 1);
            s0 += __shfl_xor_sync(0xffffffffu, s0, 2);
            s1 += __shfl_xor_sync(0xffffffffu, s1, 1);
            s1 += __shfl_xor_sync(0xffffffffu, s1, 2);
            if ((l & 3) == 0) {
                sPart[wn][rr]     = s0;
                sPart[wn][rr + 8] = s1;
            }
        }
        __syncthreads();
        if (tid < 128)
            logits[m0 + tid] = sPart[0][tid] + sPart[1][tid] + bh[0];
    }
}

// ============================================================================
// Fused softmax (sequence axis) + weighted row-sum -> out[b][H]
// ============================================================================
__global__ __launch_bounds__(256)
void softmax_weighted_kernel(const float* __restrict__ logits,
                             const float* __restrict__ X,
                             float* __restrict__ out, int N)
{
    const int b = blockIdx.x;
    logits += (long)b * N;
    X      += (long)b * N * HH;

    __shared__ float sw[2048];
    __shared__ float red[256];
    const int tid = threadIdx.x;

    float mloc = -1e30f;
    for (int i = tid; i < N; i += 256) {
        float v = logits[i];
        sw[i] = v;
        mloc = fmaxf(mloc, v);
    }
    red[tid] = mloc;
    __syncthreads();
    for (int s = 128; s > 0; s >>= 1) {
        if (tid < s) red[tid] = fmaxf(red[tid], red[tid + s]);
        __syncthreads();
    }
    const float m = red[0];
    __syncthreads();

    float sloc = 0.f;
    for (int i = tid; i < N; i += 256) {
        float e = expf(sw[i] - m);
        sw[i] = e;
        sloc += e;
    }
    red[tid] = sloc;
    __syncthreads();
    for (int s = 128; s > 0; s >>= 1) {
        if (tid < s) red[tid] += red[tid + s];
        __syncthreads();
    }
    const float inv = 1.f / red[0];
    __syncthreads();

    float acc = 0.f;
#pragma unroll 4
    for (int n = 0; n < N; ++n)
        acc = fmaf(sw[n], X[(long)n * HH + tid], acc);
    out[(long)b * HH + tid] = acc * inv;
}

// ============================================================================
extern "C" void kernel_launch(void* const* d_in, const int* in_sizes, int n_in,
                              void* d_out, int out_size)
{
    const float* v    = (const float*)d_in[0];
    const float* q    = (const float*)d_in[1];
    const float* Waff = (const float*)d_in[2];
    const float* baff = (const float*)d_in[3];
    const float* Wv   = (const float*)d_in[4];
    const float* bv   = (const float*)d_in[5];
    const float* Wq   = (const float*)d_in[6];
    const float* bq   = (const float*)d_in[7];
    const float* Whv  = (const float*)d_in[8];
    const float* bhv  = (const float*)d_in[9];
    const float* Whq  = (const float*)d_in[10];
    const float* bhq  = (const float*)d_in[11];
    float* out = (float*)d_out;

    bf16 *vhi, *vlo, *qhi, *qlo, *Wahi, *Walo, *Wvhi, *Wvlo, *Wqhi, *Wqlo;
    bf16 *vahi, *valo, *pvThi, *pvTlo, *pqThi, *pqTlo;
    bf16 *affhi, *afflo, *afThi, *afTlo;
    float *pv, *pq, *lv, *lq;
    cudaGetSymbolAddress((void**)&vhi,  g_vhi);   cudaGetSymbolAddress((void**)&vlo,  g_vlo);
    cudaGetSymbolAddress((void**)&qhi,  g_qhi);   cudaGetSymbolAddress((void**)&qlo,  g_qlo);
    cudaGetSymbolAddress((void**)&Wahi, g_Wahi);  cudaGetSymbolAddress((void**)&Walo, g_Walo);
    cudaGetSymbolAddress((void**)&Wvhi, g_Wvhi);  cudaGetSymbolAddress((void**)&Wvlo, g_Wvlo);
    cudaGetSymbolAddress((void**)&Wqhi, g_Wqhi);  cudaGetSymbolAddress((void**)&Wqlo, g_Wqlo);
    cudaGetSymbolAddress((void**)&vahi, g_vahi);  cudaGetSymbolAddress((void**)&valo, g_valo);
    cudaGetSymbolAddress((void**)&pv,   g_pv);
    cudaGetSymbolAddress((void**)&pvThi, g_pvThi); cudaGetSymbolAddress((void**)&pvTlo, g_pvTlo);
    cudaGetSymbolAddress((void**)&pq,   g_pq);
    cudaGetSymbolAddress((void**)&pqThi, g_pqThi); cudaGetSymbolAddress((void**)&pqTlo, g_pqTlo);
    cudaGetSymbolAddress((void**)&affhi, g_affhi); cudaGetSymbolAddress((void**)&afflo, g_afflo);
    cudaGetSymbolAddress((void**)&afThi, g_afThi); cudaGetSymbolAddress((void**)&afTlo, g_afTlo);
    cudaGetSymbolAddress((void**)&lv, g_lv);       cudaGetSymbolAddress((void**)&lq, g_lq);

    cudaFuncSetAttribute(mma2<0>, cudaFuncAttributeMaxDynamicSharedMemorySize, DYNSMEM);
    cudaFuncSetAttribute(mma2<1>, cudaFuncAttributeMaxDynamicSharedMemorySize, DYNSMEM);
    cudaFuncSetAttribute(mma2<2>, cudaFuncAttributeMaxDynamicSharedMemorySize, DYNSMEM);
    cudaFuncSetAttribute(mma2<3>, cudaFuncAttributeMaxDynamicSharedMemorySize, DYNSMEM);

    // 0) split inputs + weights to bf16 hi/lo
    split_kernel<<<(BB*NV*HH)/1024, 256>>>(v, vhi, vlo, (long)BB*NV*HH);
    split_kernel<<<(BB*NQ*HH)/1024, 256>>>(q, qhi, qlo, (long)BB*NQ*HH);
    split_kernel<<<(HH*HH)/1024, 256>>>(Waff, Wahi, Walo, HH*HH);
    split_kernel<<<(HA*HH)/1024, 256>>>(Wv, Wvhi, Wvlo, HA*HH);
    split_kernel<<<(HA*HH)/1024, 256>>>(Wq, Wqhi, Wqlo, HA*HH);

    // 1) va = split(v @ Waff^T + baff)     [B*NV, HH]
    mma2<0><<<dim3(HH/128, (BB*NV)/128, 1), 256, DYNSMEM>>>(
        vhi, vlo, Wahi, Walo, baff, vahi, valo, nullptr, nullptr, nullptr,
        nullptr, nullptr, nullptr, nullptr,
        HH, HH, HH, HH, 0, 0, 0, 0, 0, 0, 0, 0);

    // 2) pv = v @ Wv^T + bv (fp32) + pvT hi/lo   [B*NV, HA]
    mma2<1><<<dim3(1, (BB*NV)/128, 1), 256, DYNSMEM>>>(
        vhi, vlo, Wvhi, Wvlo, bv, nullptr, nullptr, pvThi, pvTlo, pv,
        nullptr, nullptr, nullptr, nullptr,
        HH, HH, HH, HA, NV, NV, 0, 0, 0, 0, 0, 0);

    // 3) pq = q @ Wq^T + bq (fp32) + pqT hi/lo   [B*NQ, HA]
    mma2<1><<<dim3(1, (BB*NQ)/128, 1), 256, DYNSMEM>>>(
        qhi, qlo, Wqhi, Wqlo, bq, nullptr, nullptr, pqThi, pqTlo, pq,
        nullptr, nullptr, nullptr, nullptr,
        HH, HH, HH, HA, NQ, NQ, 0, 0, 0, 0, 0, 0);

    // 4) aff = split(tanh(q @ va^T)) + affT, per batch
    mma2<2><<<dim3(NV/128, NQ/128, BB), 256, DYNSMEM>>>(
        qhi, qlo, vahi, valo, nullptr, affhi, afflo, afThi, afTlo, nullptr,
        nullptr, nullptr, nullptr, nullptr,
        HH, HH, HH, NV, NQ, 0,
        (long)NQ*HH, (long)NV*HH, (long)NQ*NV, (long)NV*NQ, 0, 0);

    // 5) logits_v = Whv . tanh(pv + affT @ pqT^T) + bhv
    mma2<3><<<dim3(NV/128, 1, BB), 256, DYNSMEM>>>(
        afThi, afTlo, pqThi, pqTlo, nullptr, nullptr, nullptr, nullptr, nullptr,
        nullptr, pv, Whv, bhv, lv,
        NQ, NQ, NQ, 0, 0, 0,
        (long)NV*NQ, (long)HA*NQ, 0, 0, (long)NV*HA, NV);

    // 6) logits_q = Whq . tanh(pq + aff @ pvT^T) + bhq
    mma2<3><<<dim3(NQ/128, 1, BB), 256, DYNSMEM>>>(
        affhi, afflo, pvThi, pvTlo, nullptr, nullptr, nullptr, nullptr, nullptr,
        nullptr, pq, Whq, bhq, lq,
        NV, NV, NV, 0, 0, 0,
        (long)NQ*NV, (long)HA*NV, 0, 0, (long)NQ*HA, NQ);

    // 7) v_hat / q_hat
    softmax_weighted_kernel<<<BB, 256>>>(lv, v, out, NV);
    softmax_weighted_kernel<<<BB, 256>>>(lq, q, out + (long)BB * HH, NQ);
}

// round 9
// speedup vs baseline: 1.6607x; 1.6607x over previous
#include <cuda_runtime.h>
#include <cuda_fp16.h>
#include <cstdint>
#include <math.h>

#define BB  64
#define NV  2048
#define NQ  512
#define HH  256
#define HA  128

// ---------------- scratch (device globals) ---------------------------------
__device__ __half g_v16[(size_t)BB*NV*HH];
__device__ __half g_q16[(size_t)BB*NQ*HH];
__device__ __half g_Wa16[HH*HH], g_Wv16[HA*HH], g_Wq16[HA*HH];
__device__ __half g_va16[(size_t)BB*NV*HH];
__device__ float  g_pv[(size_t)BB*NV*HA];
__device__ __half g_pvT16[(size_t)BB*HA*NV];
__device__ float  g_pq[(size_t)BB*NQ*HA];
__device__ __half g_pqT16[(size_t)BB*HA*NQ];
__device__ __half g_aff16[(size_t)BB*NQ*NV];
__device__ __half g_afT16[(size_t)BB*NV*NQ];
__device__ float  g_lv[BB*NV], g_lq[BB*NQ];

#define TILE_B   10240               // 128 rows * 80B
#define BUF_B    (2 * TILE_B)        // A, B
#define DYNSMEM  (2 * BUF_B)         // 40960 (double buffer)
#define PLANE_B  33280               // 128*130*2 bounce plane (fits in DYNSMEM)

// ======================= low-level helpers =================================
__device__ __forceinline__ uint32_t smem_u32(const void* p) {
    uint32_t a;
    asm("{ .reg .u64 t; cvta.to.shared.u64 t, %1; cvt.u32.u64 %0, t; }"
        : "=r"(a) : "l"(p));
    return a;
}
__device__ __forceinline__ void ldsm4(uint32_t* r, uint32_t a) {
    asm volatile("ldmatrix.sync.aligned.m8n8.x4.shared.b16 {%0,%1,%2,%3}, [%4];"
                 : "=r"(r[0]), "=r"(r[1]), "=r"(r[2]), "=r"(r[3]) : "r"(a));
}
__device__ __forceinline__ void mma_f16(float* c, const uint32_t* a,
                                        const uint32_t* b) {
    asm volatile(
        "mma.sync.aligned.m16n8k16.row.col.f32.f16.f16.f32 "
        "{%0,%1,%2,%3}, {%4,%5,%6,%7}, {%8,%9}, {%0,%1,%2,%3};"
        : "+f"(c[0]), "+f"(c[1]), "+f"(c[2]), "+f"(c[3])
        : "r"(a[0]), "r"(a[1]), "r"(a[2]), "r"(a[3]), "r"(b[0]), "r"(b[1]));
}
// pack two fp32 -> f16x2 (x -> low half)
__device__ __forceinline__ uint32_t cvt_h2(float x, float y) {
    uint32_t r;
    asm("cvt.rn.f16x2.f32 %0, %1, %2;" : "=r"(r) : "f"(y), "f"(x));
    return r;
}
__device__ __forceinline__ float tanh_fast(float x) {
    float e = __expf(2.0f * x);
    return 1.0f - __fdividef(2.0f, e + 1.0f);
}

// cp.async stage: 2 tiles (A, B), each 128 rows x 64B data -> 80B rows
__device__ __forceinline__ void stage_async(uint32_t buf,
        const __half* __restrict__ A, const __half* __restrict__ B,
        int lda, int ldb, int k0) {
    const int tid = threadIdx.x;
#pragma unroll
    for (int c = 0; c < 4; ++c) {
        const int lin = c * 256 + tid;      // 0..1023
        const int sel = lin >> 9;           // 0:A 1:B  (512 xfers per tile)
        const int li  = lin & 511;
        const int row = li >> 2, qt = li & 3;
        const __half* src = sel ? B : A;
        const int ld = sel ? ldb : lda;
        asm volatile("cp.async.cg.shared.global [%0], [%1], 16;"
            :: "r"(buf + sel * TILE_B + row * 80 + qt * 16),
               "l"((const char*)(src + (long)row * ld + k0) + qt * 16));
    }
}

// write a 128x128 fp16 smem plane (stride 130) to gmem, optional transpose
__device__ __forceinline__ void plane_out(const uint16_t* __restrict__ sm,
                                          __half* __restrict__ dst,
                                          long row0, long col0, long ld, int tr) {
    const int tid = threadIdx.x;
#pragma unroll
    for (int cI = 0; cI < 8; ++cI) {
        const int g = cI * 256 + tid;
        const int r = g >> 4, ch = g & 15;
        uint16_t e[8];
#pragma unroll
        for (int i = 0; i < 8; ++i)
            e[i] = tr ? sm[(ch * 8 + i) * 130 + r] : sm[r * 130 + ch * 8 + i];
        uint4 w;
        w.x = e[0] | ((uint32_t)e[1] << 16);
        w.y = e[2] | ((uint32_t)e[3] << 16);
        w.z = e[4] | ((uint32_t)e[5] << 16);
        w.w = e[6] | ((uint32_t)e[7] << 16);
        *(uint4*)(dst + (row0 + r) * ld + col0 + ch * 8) = w;
    }
}

// ============================================================================
// convert fp32 array -> fp16
// ============================================================================
__global__ __launch_bounds__(256)
void cvt_kernel(const float* __restrict__ x, __half* __restrict__ o, long n)
{
    const long i = ((long)blockIdx.x * 256 + threadIdx.x) * 4;
    if (i >= n) return;
    const float4 v = *(const float4*)(x + i);
    *(uint2*)((uint32_t*)o + (i >> 1)) =
        make_uint2(cvt_h2(v.x, v.y), cvt_h2(v.z, v.w));
}

// ============================================================================
// mma2: C[128-tile] = A @ B^T, fp16 operands, fp32 accumulate.
// 128x128x32 CTA tile, 8 warps (32x64), cp.async double buffer, 2 CTA/SM.
// MODE 0: C16 = f16(acc + bias)                              [va]
// MODE 1: Cf = acc + bias (fp32); CT16 = transposed f16      [pv,pq]
// MODE 2: C16 = f16(tanh(acc)); CT16 transposed              [aff]
// MODE 3: logits[m] = Wh . tanh(PAdd[m] + acc[m]) + bh       [hidden]
// ============================================================================
template<int MODE>
__global__ __launch_bounds__(256, 2)
void mma2(const __half* __restrict__ A, const __half* __restrict__ B,
          const float* __restrict__ bias,
          __half* __restrict__ C16, __half* __restrict__ CT16,
          float* __restrict__ Cf,
          const float* __restrict__ PAdd, const float* __restrict__ Wh,
          const float* __restrict__ bh, float* __restrict__ logits,
          int K, int lda, int ldb, int ldC, int ldCT, int rpb,
          long sA, long sB, long sOC, long sOCT, long sPAdd, int sLog)
{
    extern __shared__ __align__(16) unsigned char smem_[];
    __shared__ float sPart[2][128];

    const int z = blockIdx.z;
    A += z * sA;  B += z * sB;
    if (MODE == 2) { C16 += z * sOC; CT16 += z * sOCT; }
    if (MODE == 3) { PAdd += z * sPAdd; logits += (long)z * sLog; }

    const long m0 = (long)(MODE == 3 ? blockIdx.x : blockIdx.y) * 128;
    const long n0 = (MODE == 3) ? 0 : (long)blockIdx.x * 128;
    A += m0 * lda;  B += n0 * ldb;

    const uint32_t sb0 = smem_u32(smem_);
    const int tid = threadIdx.x;
    const int l = tid & 31, wid = tid >> 5;
    const int wm = wid & 3, wn = wid >> 2;

    const int sub = l >> 3, lr = l & 7;
    const uint32_t aRow = wm * 32 + ((sub & 1) << 3) + lr;
    const uint32_t aK   = (uint32_t)((sub >> 1) << 3);
    const uint32_t bRow = ((sub & 2) << 2) + lr;
    const uint32_t bK   = (uint32_t)((sub & 1) << 3);

    float acc[2][8][4] = {};

    stage_async(sb0, A, B, lda, ldb, 0);
    asm volatile("cp.async.commit_group;" ::: "memory");

    const int nchunk = K >> 5;
    for (int ch = 0; ch < nchunk; ++ch) {
        if (ch + 1 < nchunk) {
            stage_async(sb0 + ((ch + 1) & 1) * BUF_B, A, B, lda, ldb,
                        (ch + 1) * 32);
            asm volatile("cp.async.commit_group;" ::: "memory");
            asm volatile("cp.async.wait_group 1;" ::: "memory");
        } else {
            asm volatile("cp.async.wait_group 0;" ::: "memory");
        }
        __syncthreads();

        const uint32_t cur = sb0 + (ch & 1) * BUF_B;
        const uint32_t sA = cur, sB = cur + TILE_B;

#pragma unroll
        for (int kt = 0; kt < 32; kt += 16) {
            uint32_t Af[2][4];
            const uint32_t ak = (kt + aK) * 2;
#pragma unroll
            for (int mt = 0; mt < 2; ++mt)
                ldsm4(Af[mt], sA + (aRow + mt * 16) * 80 + ak);
            const uint32_t bk = (kt + bK) * 2;
#pragma unroll
            for (int g = 0; g < 4; ++g) {
                uint32_t Bf[4];
                ldsm4(Bf, sB + (wn * 64 + g * 16 + bRow) * 80 + bk);
                mma_f16(acc[0][2*g],   Af[0], &Bf[0]);
                mma_f16(acc[0][2*g+1], Af[0], &Bf[2]);
                mma_f16(acc[1][2*g],   Af[1], &Bf[0]);
                mma_f16(acc[1][2*g+1], Af[1], &Bf[2]);
            }
        }
        __syncthreads();
    }

    // ---------------- epilogues ----------------
    if (MODE == 0) {
#pragma unroll
        for (int mt = 0; mt < 2; ++mt) {
            const long r0 = m0 + wm * 32 + mt * 16 + (l >> 2);
#pragma unroll
            for (int nt = 0; nt < 8; ++nt) {
                const long col = n0 + wn * 64 + nt * 8 + 2 * (l & 3);
                const float2 b2 = *(const float2*)&bias[col];
                ((uint32_t*)C16)[(r0 * (long)ldC + col) >> 1] =
                    cvt_h2(acc[mt][nt][0] + b2.x, acc[mt][nt][1] + b2.y);
                ((uint32_t*)C16)[((r0 + 8) * (long)ldC + col) >> 1] =
                    cvt_h2(acc[mt][nt][2] + b2.x, acc[mt][nt][3] + b2.y);
            }
        }
    } else if (MODE == 1 || MODE == 2) {
        uint32_t* pl = (uint32_t*)smem_;
#pragma unroll
        for (int mt = 0; mt < 2; ++mt) {
            const int rl = wm * 32 + mt * 16 + (l >> 2);
#pragma unroll
            for (int nt = 0; nt < 8; ++nt) {
                const int c = wn * 64 + nt * 8 + 2 * (l & 3);
                float v0 = acc[mt][nt][0], v1 = acc[mt][nt][1];
                float v2 = acc[mt][nt][2], v3 = acc[mt][nt][3];
                if (MODE == 1) {
                    const float2 b2 = *(const float2*)&bias[n0 + c];
                    v0 += b2.x; v1 += b2.y; v2 += b2.x; v3 += b2.y;
                    const long r0 = m0 + rl;
                    *(float2*)&Cf[r0 * (long)ldC + n0 + c]       = make_float2(v0, v1);
                    *(float2*)&Cf[(r0 + 8) * (long)ldC + n0 + c] = make_float2(v2, v3);
                } else {
                    v0 = tanh_fast(v0); v1 = tanh_fast(v1);
                    v2 = tanh_fast(v2); v3 = tanh_fast(v3);
                }
                pl[(rl * 130 + c) >> 1]       = cvt_h2(v0, v1);
                pl[((rl + 8) * 130 + c) >> 1] = cvt_h2(v2, v3);
            }
        }
        __syncthreads();
        const uint16_t* sm = (const uint16_t*)smem_;
        if (MODE == 1) {
            const long b = m0 / rpb, nIn = m0 - b * rpb;
            plane_out(sm, CT16, b * HA, nIn, ldCT, 1);
        } else {
            plane_out(sm, C16,  m0, n0, ldC, 0);
            plane_out(sm, CT16, n0, m0, ldCT, 1);
        }
    } else {  // MODE 3
        float2 whr[8];
#pragma unroll
        for (int nt = 0; nt < 8; ++nt)
            whr[nt] = *(const float2*)&Wh[wn * 64 + nt * 8 + 2 * (l & 3)];
#pragma unroll
        for (int mt = 0; mt < 2; ++mt) {
            const int rr = wm * 32 + mt * 16 + (l >> 2);
            float s0 = 0.f, s1 = 0.f;
#pragma unroll
            for (int nt = 0; nt < 8; ++nt) {
                const int col = wn * 64 + nt * 8 + 2 * (l & 3);
                const float2 w = whr[nt];
                const float2 p0 = *(const float2*)&PAdd[(m0 + rr) * (long)HA + col];
                const float2 p1 = *(const float2*)&PAdd[(m0 + rr + 8) * (long)HA + col];
                s0 += w.x * tanh_fast(p0.x + acc[mt][nt][0])
                    + w.y * tanh_fast(p0.y + acc[mt][nt][1]);
                s1 += w.x * tanh_fast(p1.x + acc[mt][nt][2])
                    + w.y * tanh_fast(p1.y + acc[mt][nt][3]);
            }
            s0 += __shfl_xor_sync(0xffffffffu, s0, 1);
            s0 += __shfl_xor_sync(0xffffffffu, s0, 2);
            s1 += __shfl_xor_sync(0xffffffffu, s1, 1);
            s1 += __shfl_xor_sync(0xffffffffu, s1, 2);
            if ((l & 3) == 0) {
                sPart[wn][rr]     = s0;
                sPart[wn][rr + 8] = s1;
            }
        }
        __syncthreads();
        if (tid < 128)
            logits[m0 + tid] = sPart[0][tid] + sPart[1][tid] + bh[0];
    }
}

// ============================================================================
// Fused softmax (sequence axis) + weighted row-sum -> out[b][H]
// ============================================================================
__global__ __launch_bounds__(256)
void softmax_weighted_kernel(const float* __restrict__ logits,
                             const float* __restrict__ X,
                             float* __restrict__ out, int N)
{
    const int b = blockIdx.x;
    logits += (long)b * N;
    X      += (long)b * N * HH;

    __shared__ float sw[2048];
    __shared__ float red[256];
    const int tid = threadIdx.x;

    float mloc = -1e30f;
    for (int i = tid; i < N; i += 256) {
        float v = logits[i];
        sw[i] = v;
        mloc = fmaxf(mloc, v);
    }
    red[tid] = mloc;
    __syncthreads();
    for (int s = 128; s > 0; s >>= 1) {
        if (tid < s) red[tid] = fmaxf(red[tid], red[tid + s]);
        __syncthreads();
    }
    const float m = red[0];
    __syncthreads();

    float sloc = 0.f;
    for (int i = tid; i < N; i += 256) {
        float e = expf(sw[i] - m);
        sw[i] = e;
        sloc += e;
    }
    red[tid] = sloc;
    __syncthreads();
    for (int s = 128; s > 0; s >>= 1) {
        if (tid < s) red[tid] += red[tid + s];
        __syncthreads();
    }
    const float inv = 1.f / red[0];
    __syncthreads();

    float acc = 0.f;
#pragma unroll 4
    for (int n = 0; n < N; ++n)
        acc = fmaf(sw[n], X[(long)n * HH + tid], acc);
    out[(long)b * HH + tid] = acc * inv;
}

// ============================================================================
extern "C" void kernel_launch(void* const* d_in, const int* in_sizes, int n_in,
                              void* d_out, int out_size)
{
    const float* v    = (const float*)d_in[0];
    const float* q    = (const float*)d_in[1];
    const float* Waff = (const float*)d_in[2];
    const float* baff = (const float*)d_in[3];
    const float* Wv   = (const float*)d_in[4];
    const float* bv   = (const float*)d_in[5];
    const float* Wq   = (const float*)d_in[6];
    const float* bq   = (const float*)d_in[7];
    const float* Whv  = (const float*)d_in[8];
    const float* bhv  = (const float*)d_in[9];
    const float* Whq  = (const float*)d_in[10];
    const float* bhq  = (const float*)d_in[11];
    float* out = (float*)d_out;

    __half *v16, *q16, *Wa16, *Wv16, *Wq16, *va16, *pvT16, *pqT16, *aff16, *afT16;
    float *pv, *pq, *lv, *lq;
    cudaGetSymbolAddress((void**)&v16,   g_v16);
    cudaGetSymbolAddress((void**)&q16,   g_q16);
    cudaGetSymbolAddress((void**)&Wa16,  g_Wa16);
    cudaGetSymbolAddress((void**)&Wv16,  g_Wv16);
    cudaGetSymbolAddress((void**)&Wq16,  g_Wq16);
    cudaGetSymbolAddress((void**)&va16,  g_va16);
    cudaGetSymbolAddress((void**)&pv,    g_pv);
    cudaGetSymbolAddress((void**)&pvT16, g_pvT16);
    cudaGetSymbolAddress((void**)&pq,    g_pq);
    cudaGetSymbolAddress((void**)&pqT16, g_pqT16);
    cudaGetSymbolAddress((void**)&aff16, g_aff16);
    cudaGetSymbolAddress((void**)&afT16, g_afT16);
    cudaGetSymbolAddress((void**)&lv,    g_lv);
    cudaGetSymbolAddress((void**)&lq,    g_lq);

    cudaFuncSetAttribute(mma2<0>, cudaFuncAttributeMaxDynamicSharedMemorySize, DYNSMEM);
    cudaFuncSetAttribute(mma2<1>, cudaFuncAttributeMaxDynamicSharedMemorySize, DYNSMEM);
    cudaFuncSetAttribute(mma2<2>, cudaFuncAttributeMaxDynamicSharedMemorySize, DYNSMEM);
    cudaFuncSetAttribute(mma2<3>, cudaFuncAttributeMaxDynamicSharedMemorySize, DYNSMEM);

    // 0) convert inputs + weights to fp16
    cvt_kernel<<<(BB*NV*HH)/1024, 256>>>(v, v16, (long)BB*NV*HH);
    cvt_kernel<<<(BB*NQ*HH)/1024, 256>>>(q, q16, (long)BB*NQ*HH);
    cvt_kernel<<<(HH*HH)/1024, 256>>>(Waff, Wa16, HH*HH);
    cvt_kernel<<<(HA*HH)/1024, 256>>>(Wv, Wv16, HA*HH);
    cvt_kernel<<<(HA*HH)/1024, 256>>>(Wq, Wq16, HA*HH);

    // 1) va16 = f16(v @ Waff^T + baff)     [B*NV, HH]
    mma2<0><<<dim3(HH/128, (BB*NV)/128, 1), 256, DYNSMEM>>>(
        v16, Wa16, baff, va16, nullptr, nullptr,
        nullptr, nullptr, nullptr, nullptr,
        HH, HH, HH, HH, 0, 0, 0, 0, 0, 0, 0, 0);

    // 2) pv = v @ Wv^T + bv (fp32) + pvT16   [B*NV, HA]
    mma2<1><<<dim3(1, (BB*NV)/128, 1), 256, DYNSMEM>>>(
        v16, Wv16, bv, nullptr, pvT16, pv,
        nullptr, nullptr, nullptr, nullptr,
        HH, HH, HH, HA, NV, NV, 0, 0, 0, 0, 0, 0);

    // 3) pq = q @ Wq^T + bq (fp32) + pqT16   [B*NQ, HA]
    mma2<1><<<dim3(1, (BB*NQ)/128, 1), 256, DYNSMEM>>>(
        q16, Wq16, bq, nullptr, pqT16, pq,
        nullptr, nullptr, nullptr, nullptr,
        HH, HH, HH, HA, NQ, NQ, 0, 0, 0, 0, 0, 0);

    // 4) aff16 = f16(tanh(q @ va^T)) + afT16, per batch
    mma2<2><<<dim3(NV/128, NQ/128, BB), 256, DYNSMEM>>>(
        q16, va16, nullptr, aff16, afT16, nullptr,
        nullptr, nullptr, nullptr, nullptr,
        HH, HH, HH, NV, NQ, 0,
        (long)NQ*HH, (long)NV*HH, (long)NQ*NV, (long)NV*NQ, 0, 0);

    // 5) logits_v = Whv . tanh(pv + afT @ pqT^T) + bhv
    mma2<3><<<dim3(NV/128, 1, BB), 256, DYNSMEM>>>(
        afT16, pqT16, nullptr, nullptr, nullptr, nullptr,
        pv, Whv, bhv, lv,
        NQ, NQ, NQ, 0, 0, 0,
        (long)NV*NQ, (long)HA*NQ, 0, 0, (long)NV*HA, NV);

    // 6) logits_q = Whq . tanh(pq + aff @ pvT^T) + bhq
    mma2<3><<<dim3(NQ/128, 1, BB), 256, DYNSMEM>>>(
        aff16, pvT16, nullptr, nullptr, nullptr, nullptr,
        pq, Whq, bhq, lq,
        NV, NV, NV, 0, 0, 0,
        (long)NQ*NV, (long)HA*NV, 0, 0, (long)NQ*HA, NQ);

    // 7) v_hat / q_hat
    softmax_weighted_kernel<<<BB, 256>>>(lv, v, out, NV);
    softmax_weighted_kernel<<<BB, 256>>>(lq, q, out + (long)BB * HH, NQ);
}

// round 10
// speedup vs baseline: 1.7560x; 1.0574x over previous
#include <cuda_runtime.h>
#include <cuda_fp16.h>
#include <cstdint>
#include <math.h>

#define BB  64
#define NV  2048
#define NQ  512
#define HH  256
#define HA  128

// ---------------- scratch (device globals) ---------------------------------
__device__ __half g_v16[(size_t)BB*NV*HH];
__device__ __half g_q16[(size_t)BB*NQ*HH];
__device__ __half g_WaT16[HH*HH];               // Waff^T (for qW = q @ Waff)
__device__ __half g_Wv16[HA*HH], g_Wq16[HA*HH];
__device__ __half g_qW16[(size_t)BB*NQ*HH];     // q @ Waff
__device__ float  g_qb[BB*NQ];                  // q . baff  (per-row scalar)
__device__ float  g_pv[(size_t)BB*NV*HA];
__device__ __half g_pvT16[(size_t)BB*HA*NV];
__device__ float  g_pq[(size_t)BB*NQ*HA];
__device__ __half g_pqT16[(size_t)BB*HA*NQ];
__device__ __half g_aff16[(size_t)BB*NQ*NV];
__device__ __half g_afT16[(size_t)BB*NV*NQ];
__device__ float  g_lv[BB*NV], g_lq[BB*NQ];
__device__ float2 g_norm[BB];
__device__ float  g_part[BB*8*HH];

#define TILE_B   10240               // 128 rows * 80B
#define BUF_B    (2 * TILE_B)        // A, B
#define DYNSMEM  (2 * BUF_B)         // 40960 (double buffer)
#define PLANE_B  33280               // 128*130*2 bounce plane (fits in DYNSMEM)

// ======================= low-level helpers =================================
__device__ __forceinline__ uint32_t smem_u32(const void* p) {
    uint32_t a;
    asm("{ .reg .u64 t; cvta.to.shared.u64 t, %1; cvt.u32.u64 %0, t; }"
        : "=r"(a) : "l"(p));
    return a;
}
__device__ __forceinline__ void ldsm4(uint32_t* r, uint32_t a) {
    asm volatile("ldmatrix.sync.aligned.m8n8.x4.shared.b16 {%0,%1,%2,%3}, [%4];"
                 : "=r"(r[0]), "=r"(r[1]), "=r"(r[2]), "=r"(r[3]) : "r"(a));
}
__device__ __forceinline__ void mma_f16(float* c, const uint32_t* a,
                                        const uint32_t* b) {
    asm volatile(
        "mma.sync.aligned.m16n8k16.row.col.f32.f16.f16.f32 "
        "{%0,%1,%2,%3}, {%4,%5,%6,%7}, {%8,%9}, {%0,%1,%2,%3};"
        : "+f"(c[0]), "+f"(c[1]), "+f"(c[2]), "+f"(c[3])
        : "r"(a[0]), "r"(a[1]), "r"(a[2]), "r"(a[3]), "r"(b[0]), "r"(b[1]));
}
__device__ __forceinline__ uint32_t cvt_h2(float x, float y) {
    uint32_t r;
    asm("cvt.rn.f16x2.f32 %0, %1, %2;" : "=r"(r) : "f"(y), "f"(x));
    return r;
}
__device__ __forceinline__ float tanh_fast(float x) {
    float e = __expf(2.0f * x);
    return 1.0f - __fdividef(2.0f, e + 1.0f);
}

// cp.async stage: 2 tiles (A, B), each 128 rows x 64B data -> 80B rows
__device__ __forceinline__ void stage_async(uint32_t buf,
        const __half* __restrict__ A, const __half* __restrict__ B,
        int lda, int ldb, int k0) {
    const int tid = threadIdx.x;
#pragma unroll
    for (int c = 0; c < 4; ++c) {
        const int lin = c * 256 + tid;
        const int sel = lin >> 9;
        const int li  = lin & 511;
        const int row = li >> 2, qt = li & 3;
        const __half* src = sel ? B : A;
        const int ld = sel ? ldb : lda;
        asm volatile("cp.async.cg.shared.global [%0], [%1], 16;"
            :: "r"(buf + sel * TILE_B + row * 80 + qt * 16),
               "l"((const char*)(src + (long)row * ld + k0) + qt * 16));
    }
}

// write a 128x128 fp16 smem plane (stride 130) to gmem, optional transpose
__device__ __forceinline__ void plane_out(const uint16_t* __restrict__ sm,
                                          __half* __restrict__ dst,
                                          long row0, long col0, long ld, int tr) {
    const int tid = threadIdx.x;
#pragma unroll
    for (int cI = 0; cI < 8; ++cI) {
        const int g = cI * 256 + tid;
        const int r = g >> 4, ch = g & 15;
        uint16_t e[8];
#pragma unroll
        for (int i = 0; i < 8; ++i)
            e[i] = tr ? sm[(ch * 8 + i) * 130 + r] : sm[r * 130 + ch * 8 + i];
        uint4 w;
        w.x = e[0] | ((uint32_t)e[1] << 16);
        w.y = e[2] | ((uint32_t)e[3] << 16);
        w.z = e[4] | ((uint32_t)e[5] << 16);
        w.w = e[6] | ((uint32_t)e[7] << 16);
        *(uint4*)(dst + (row0 + r) * ld + col0 + ch * 8) = w;
    }
}

// ============================================================================
// small conversion / prep kernels
// ============================================================================
__global__ __launch_bounds__(256)
void cvt_kernel(const float* __restrict__ x, __half* __restrict__ o, long n)
{
    const long i = ((long)blockIdx.x * 256 + threadIdx.x) * 4;
    if (i >= n) return;
    const float4 v = *(const float4*)(x + i);
    *(uint2*)((uint32_t*)o + (i >> 1)) =
        make_uint2(cvt_h2(v.x, v.y), cvt_h2(v.z, v.w));
}

// o[c*R + r] = f16(x[r*C + c])  (transpose convert, small matrices)
__global__ __launch_bounds__(256)
void cvtT_kernel(const float* __restrict__ x, __half* __restrict__ o,
                 int R, int C)
{
    const int i = blockIdx.x * 256 + threadIdx.x;
    if (i >= R * C) return;
    const int r = i / C, c = i - r * C;
    o[(long)c * R + r] = __float2half(x[i]);
}

// qb[row] = q[row,:] . baff   (one warp per row)
__global__ __launch_bounds__(256)
void qb_kernel(const float* __restrict__ q, const float* __restrict__ baff,
               float* __restrict__ qb, int rows)
{
    const int w = (blockIdx.x * 256 + threadIdx.x) >> 5;
    const int lane = threadIdx.x & 31;
    if (w >= rows) return;
    const float* r = q + (long)w * HH;
    float s = 0.f;
#pragma unroll
    for (int k = 0; k < 8; ++k)
        s += r[lane + 32 * k] * baff[lane + 32 * k];
#pragma unroll
    for (int off = 16; off > 0; off >>= 1)
        s += __shfl_xor_sync(0xffffffffu, s, off);
    if (lane == 0) qb[w] = s;
}

// ============================================================================
// mma2: C[128-tile] = A @ B^T, fp16 operands, fp32 accumulate.
// 128x128x32 CTA tile, 8 warps (32x64), cp.async double buffer, 2 CTA/SM.
// MODE 0: C16 = f16(acc [+ bias])                            [qW]
// MODE 1: Cf = acc + bias (fp32); CT16 = transposed f16      [pv,pq]
// MODE 2: C16 = f16(tanh(acc + rowB[m])); CT16 transposed    [aff]
// MODE 3: logits[m] = Wh . tanh(PAdd[m] + acc[m]) + bh       [hidden]
// ============================================================================
template<int MODE>
__global__ __launch_bounds__(256, 2)
void mma2(const __half* __restrict__ A, const __half* __restrict__ B,
          const float* __restrict__ bias, const float* __restrict__ rowB,
          __half* __restrict__ C16, __half* __restrict__ CT16,
          float* __restrict__ Cf,
          const float* __restrict__ PAdd, const float* __restrict__ Wh,
          const float* __restrict__ bh, float* __restrict__ logits,
          int K, int lda, int ldb, int ldC, int ldCT, int rpb,
          long sA, long sB, long sOC, long sOCT, long sPAdd, int sLog)
{
    extern __shared__ __align__(16) unsigned char smem_[];
    __shared__ float sPart[2][128];

    const int z = blockIdx.z;
    A += z * sA;  B += z * sB;
    if (MODE == 2) { C16 += z * sOC; CT16 += z * sOCT; rowB += (long)z * NQ; }
    if (MODE == 3) { PAdd += z * sPAdd; logits += (long)z * sLog; }

    const long m0 = (long)(MODE == 3 ? blockIdx.x : blockIdx.y) * 128;
    const long n0 = (MODE == 3) ? 0 : (long)blockIdx.x * 128;
    A += m0 * lda;  B += n0 * ldb;

    const uint32_t sb0 = smem_u32(smem_);
    const int tid = threadIdx.x;
    const int l = tid & 31, wid = tid >> 5;
    const int wm = wid & 3, wn = wid >> 2;

    const int sub = l >> 3, lr = l & 7;
    const uint32_t aRow = wm * 32 + ((sub & 1) << 3) + lr;
    const uint32_t aK   = (uint32_t)((sub >> 1) << 3);
    const uint32_t bRow = ((sub & 2) << 2) + lr;
    const uint32_t bK   = (uint32_t)((sub & 1) << 3);

    float acc[2][8][4] = {};

    stage_async(sb0, A, B, lda, ldb, 0);
    asm volatile("cp.async.commit_group;" ::: "memory");

    const int nchunk = K >> 5;
    for (int ch = 0; ch < nchunk; ++ch) {
        if (ch + 1 < nchunk) {
            stage_async(sb0 + ((ch + 1) & 1) * BUF_B, A, B, lda, ldb,
                        (ch + 1) * 32);
            asm volatile("cp.async.commit_group;" ::: "memory");
            asm volatile("cp.async.wait_group 1;" ::: "memory");
        } else {
            asm volatile("cp.async.wait_group 0;" ::: "memory");
        }
        __syncthreads();

        const uint32_t cur = sb0 + (ch & 1) * BUF_B;
        const uint32_t sA = cur, sB = cur + TILE_B;

#pragma unroll
        for (int kt = 0; kt < 32; kt += 16) {
            uint32_t Af[2][4];
            const uint32_t ak = (kt + aK) * 2;
#pragma unroll
            for (int mt = 0; mt < 2; ++mt)
                ldsm4(Af[mt], sA + (aRow + mt * 16) * 80 + ak);
            const uint32_t bk = (kt + bK) * 2;
#pragma unroll
            for (int g = 0; g < 4; ++g) {
                uint32_t Bf[4];
                ldsm4(Bf, sB + (wn * 64 + g * 16 + bRow) * 80 + bk);
                mma_f16(acc[0][2*g],   Af[0], &Bf[0]);
                mma_f16(acc[0][2*g+1], Af[0], &Bf[2]);
                mma_f16(acc[1][2*g],   Af[1], &Bf[0]);
                mma_f16(acc[1][2*g+1], Af[1], &Bf[2]);
            }
        }
        __syncthreads();
    }

    // ---------------- epilogues ----------------
    if (MODE == 0) {
#pragma unroll
        for (int mt = 0; mt < 2; ++mt) {
            const long r0 = m0 + wm * 32 + mt * 16 + (l >> 2);
#pragma unroll
            for (int nt = 0; nt < 8; ++nt) {
                const long col = n0 + wn * 64 + nt * 8 + 2 * (l & 3);
                float2 b2 = bias ? *(const float2*)&bias[col]
                                 : make_float2(0.f, 0.f);
                ((uint32_t*)C16)[(r0 * (long)ldC + col) >> 1] =
                    cvt_h2(acc[mt][nt][0] + b2.x, acc[mt][nt][1] + b2.y);
                ((uint32_t*)C16)[((r0 + 8) * (long)ldC + col) >> 1] =
                    cvt_h2(acc[mt][nt][2] + b2.x, acc[mt][nt][3] + b2.y);
            }
        }
    } else if (MODE == 1 || MODE == 2) {
        uint32_t* pl = (uint32_t*)smem_;
#pragma unroll
        for (int mt = 0; mt < 2; ++mt) {
            const int rl = wm * 32 + mt * 16 + (l >> 2);
            float rb0 = 0.f, rb1 = 0.f;
            if (MODE == 2) {
                rb0 = rowB[m0 + rl];
                rb1 = rowB[m0 + rl + 8];
            }
#pragma unroll
            for (int nt = 0; nt < 8; ++nt) {
                const int c = wn * 64 + nt * 8 + 2 * (l & 3);
                float v0 = acc[mt][nt][0], v1 = acc[mt][nt][1];
                float v2 = acc[mt][nt][2], v3 = acc[mt][nt][3];
                if (MODE == 1) {
                    const float2 b2 = *(const float2*)&bias[n0 + c];
                    v0 += b2.x; v1 += b2.y; v2 += b2.x; v3 += b2.y;
                    const long r0 = m0 + rl;
                    *(float2*)&Cf[r0 * (long)ldC + n0 + c]       = make_float2(v0, v1);
                    *(float2*)&Cf[(r0 + 8) * (long)ldC + n0 + c] = make_float2(v2, v3);
                } else {
                    v0 = tanh_fast(v0 + rb0); v1 = tanh_fast(v1 + rb0);
                    v2 = tanh_fast(v2 + rb1); v3 = tanh_fast(v3 + rb1);
                }
                pl[(rl * 130 + c) >> 1]       = cvt_h2(v0, v1);
                pl[((rl + 8) * 130 + c) >> 1] = cvt_h2(v2, v3);
            }
        }
        __syncthreads();
        const uint16_t* sm = (const uint16_t*)smem_;
        if (MODE == 1) {
            const long b = m0 / rpb, nIn = m0 - b * rpb;
            plane_out(sm, CT16, b * HA, nIn, ldCT, 1);
        } else {
            plane_out(sm, C16,  m0, n0, ldC, 0);
            plane_out(sm, CT16, n0, m0, ldCT, 1);
        }
    } else {  // MODE 3
        float2 whr[8];
#pragma unroll
        for (int nt = 0; nt < 8; ++nt)
            whr[nt] = *(const float2*)&Wh[wn * 64 + nt * 8 + 2 * (l & 3)];
#pragma unroll
        for (int mt = 0; mt < 2; ++mt) {
            const int rr = wm * 32 + mt * 16 + (l >> 2);
            float s0 = 0.f, s1 = 0.f;
#pragma unroll
            for (int nt = 0; nt < 8; ++nt) {
                const int col = wn * 64 + nt * 8 + 2 * (l & 3);
                const float2 w = whr[nt];
                const float2 p0 = *(const float2*)&PAdd[(m0 + rr) * (long)HA + col];
                const float2 p1 = *(const float2*)&PAdd[(m0 + rr + 8) * (long)HA + col];
                s0 += w.x * tanh_fast(p0.x + acc[mt][nt][0])
                    + w.y * tanh_fast(p0.y + acc[mt][nt][1]);
                s1 += w.x * tanh_fast(p1.x + acc[mt][nt][2])
                    + w.y * tanh_fast(p1.y + acc[mt][nt][3]);
            }
            s0 += __shfl_xor_sync(0xffffffffu, s0, 1);
            s0 += __shfl_xor_sync(0xffffffffu, s0, 2);
            s1 += __shfl_xor_sync(0xffffffffu, s1, 1);
            s1 += __shfl_xor_sync(0xffffffffu, s1, 2);
            if ((l & 3) == 0) {
                sPart[wn][rr]     = s0;
                sPart[wn][rr + 8] = s1;
            }
        }
        __syncthreads();
        if (tid < 128)
            logits[m0 + tid] = sPart[0][tid] + sPart[1][tid] + bh[0];
    }
}

// ============================================================================
// Parallel softmax + weighted sum (3 stages)
// ============================================================================
__global__ __launch_bounds__(256)
void norm_kernel(const float* __restrict__ logits, float2* __restrict__ norm,
                 int N)
{
    const int b = blockIdx.x;
    logits += (long)b * N;
    __shared__ float sw[2048];
    __shared__ float red[256];
    const int tid = threadIdx.x;

    float mloc = -1e30f;
    for (int i = tid; i < N; i += 256) {
        float v = logits[i];
        sw[i] = v;
        mloc = fmaxf(mloc, v);
    }
    red[tid] = mloc;
    __syncthreads();
    for (int s = 128; s > 0; s >>= 1) {
        if (tid < s) red[tid] = fmaxf(red[tid], red[tid + s]);
        __syncthreads();
    }
    const float m = red[0];
    __syncthreads();

    float sloc = 0.f;
    for (int i = tid; i < N; i += 256)
        sloc += expf(sw[i] - m);
    red[tid] = sloc;
    __syncthreads();
    for (int s = 128; s > 0; s >>= 1) {
        if (tid < s) red[tid] += red[tid + s];
        __syncthreads();
    }
    if (tid == 0) norm[b] = make_float2(m, 1.f / red[0]);
}

__global__ __launch_bounds__(256)
void wsum_kernel(const float* __restrict__ logits, const float* __restrict__ X,
                 const float2* __restrict__ norm, float* __restrict__ part,
                 int N)
{
    const int b = blockIdx.y, c = blockIdx.x;    // c in [0,8)
    const int CH = N >> 3;
    logits += (long)b * N + c * CH;
    X      += ((long)b * N + (long)c * CH) * HH;

    __shared__ float sw[256];
    const int tid = threadIdx.x;
    const float m = norm[b].x;
    for (int i = tid; i < CH; i += 256)
        sw[i] = expf(logits[i] - m);
    __syncthreads();

    float acc = 0.f;
#pragma unroll 4
    for (int n = 0; n < CH; ++n)
        acc = fmaf(sw[n], X[(long)n * HH + tid], acc);
    part[((b << 3) + c) * HH + tid] = acc;
}

__global__ __launch_bounds__(256)
void reduce_kernel(const float* __restrict__ part,
                   const float2* __restrict__ norm, float* __restrict__ out)
{
    const int b = blockIdx.x, tid = threadIdx.x;
    float s = 0.f;
#pragma unroll
    for (int c = 0; c < 8; ++c)
        s += part[((b << 3) + c) * HH + tid];
    out[(long)b * HH + tid] = s * norm[b].y;
}

// ============================================================================
extern "C" void kernel_launch(void* const* d_in, const int* in_sizes, int n_in,
                              void* d_out, int out_size)
{
    const float* v    = (const float*)d_in[0];
    const float* q    = (const float*)d_in[1];
    const float* Waff = (const float*)d_in[2];
    const float* baff = (const float*)d_in[3];
    const float* Wv   = (const float*)d_in[4];
    const float* bv   = (const float*)d_in[5];
    const float* Wq   = (const float*)d_in[6];
    const float* bq   = (const float*)d_in[7];
    const float* Whv  = (const float*)d_in[8];
    const float* bhv  = (const float*)d_in[9];
    const float* Whq  = (const float*)d_in[10];
    const float* bhq  = (const float*)d_in[11];
    float* out = (float*)d_out;

    __half *v16, *q16, *WaT16, *Wv16, *Wq16, *qW16, *pvT16, *pqT16, *aff16, *afT16;
    float *qb, *pv, *pq, *lv, *lq, *part;
    float2* nrm;
    cudaGetSymbolAddress((void**)&v16,   g_v16);
    cudaGetSymbolAddress((void**)&q16,   g_q16);
    cudaGetSymbolAddress((void**)&WaT16, g_WaT16);
    cudaGetSymbolAddress((void**)&Wv16,  g_Wv16);
    cudaGetSymbolAddress((void**)&Wq16,  g_Wq16);
    cudaGetSymbolAddress((void**)&qW16,  g_qW16);
    cudaGetSymbolAddress((void**)&qb,    g_qb);
    cudaGetSymbolAddress((void**)&pv,    g_pv);
    cudaGetSymbolAddress((void**)&pvT16, g_pvT16);
    cudaGetSymbolAddress((void**)&pq,    g_pq);
    cudaGetSymbolAddress((void**)&pqT16, g_pqT16);
    cudaGetSymbolAddress((void**)&aff16, g_aff16);
    cudaGetSymbolAddress((void**)&afT16, g_afT16);
    cudaGetSymbolAddress((void**)&lv,    g_lv);
    cudaGetSymbolAddress((void**)&lq,    g_lq);
    cudaGetSymbolAddress((void**)&nrm,   g_norm);
    cudaGetSymbolAddress((void**)&part,  g_part);

    cudaFuncSetAttribute(mma2<0>, cudaFuncAttributeMaxDynamicSharedMemorySize, DYNSMEM);
    cudaFuncSetAttribute(mma2<1>, cudaFuncAttributeMaxDynamicSharedMemorySize, DYNSMEM);
    cudaFuncSetAttribute(mma2<2>, cudaFuncAttributeMaxDynamicSharedMemorySize, DYNSMEM);
    cudaFuncSetAttribute(mma2<3>, cudaFuncAttributeMaxDynamicSharedMemorySize, DYNSMEM);

    // 0) conversions + row-bias
    cvt_kernel<<<(BB*NV*HH)/1024, 256>>>(v, v16, (long)BB*NV*HH);
    cvt_kernel<<<(BB*NQ*HH)/1024, 256>>>(q, q16, (long)BB*NQ*HH);
    cvtT_kernel<<<(HH*HH)/256, 256>>>(Waff, WaT16, HH, HH);
    cvt_kernel<<<(HA*HH)/1024, 256>>>(Wv, Wv16, HA*HH);
    cvt_kernel<<<(HA*HH)/1024, 256>>>(Wq, Wq16, HA*HH);
    qb_kernel<<<(BB*NQ)/8, 256>>>(q, baff, qb, BB*NQ);

    // 1) qW16 = f16(q @ Waff)   [B*NQ, HH]  (A@B^T with B = Waff^T)
    mma2<0><<<dim3(HH/128, (BB*NQ)/128, 1), 256, DYNSMEM>>>(
        q16, WaT16, nullptr, nullptr, qW16, nullptr, nullptr,
        nullptr, nullptr, nullptr, nullptr,
        HH, HH, HH, HH, 0, 0, 0, 0, 0, 0, 0, 0);

    // 2) pv = v @ Wv^T + bv (fp32) + pvT16   [B*NV, HA]
    mma2<1><<<dim3(1, (BB*NV)/128, 1), 256, DYNSMEM>>>(
        v16, Wv16, bv, nullptr, nullptr, pvT16, pv,
        nullptr, nullptr, nullptr, nullptr,
        HH, HH, HH, HA, NV, NV, 0, 0, 0, 0, 0, 0);

    // 3) pq = q @ Wq^T + bq (fp32) + pqT16   [B*NQ, HA]
    mma2<1><<<dim3(1, (BB*NQ)/128, 1), 256, DYNSMEM>>>(
        q16, Wq16, bq, nullptr, nullptr, pqT16, pq,
        nullptr, nullptr, nullptr, nullptr,
        HH, HH, HH, HA, NQ, NQ, 0, 0, 0, 0, 0, 0);

    // 4) aff16/afT16 = f16(tanh(qW @ v^T + qb[row])), per batch
    mma2<2><<<dim3(NV/128, NQ/128, BB), 256, DYNSMEM>>>(
        qW16, v16, nullptr, qb, aff16, afT16, nullptr,
        nullptr, nullptr, nullptr, nullptr,
        HH, HH, HH, NV, NQ, 0,
        (long)NQ*HH, (long)NV*HH, (long)NQ*NV, (long)NV*NQ, 0, 0);

    // 5) logits_v = Whv . tanh(pv + afT @ pqT^T) + bhv
    mma2<3><<<dim3(NV/128, 1, BB), 256, DYNSMEM>>>(
        afT16, pqT16, nullptr, nullptr, nullptr, nullptr, nullptr,
        pv, Whv, bhv, lv,
        NQ, NQ, NQ, 0, 0, 0,
        (long)NV*NQ, (long)HA*NQ, 0, 0, (long)NV*HA, NV);

    // 6) logits_q = Whq . tanh(pq + aff @ pvT^T) + bhq
    mma2<3><<<dim3(NQ/128, 1, BB), 256, DYNSMEM>>>(
        aff16, pvT16, nullptr, nullptr, nullptr, nullptr, nullptr,
        pq, Whq, bhq, lq,
        NV, NV, NV, 0, 0, 0,
        (long)NQ*NV, (long)HA*NV, 0, 0, (long)NQ*HA, NQ);

    // 7) v_hat: softmax(lv) . v
    norm_kernel<<<BB, 256>>>(lv, nrm, NV);
    wsum_kernel<<<dim3(8, BB), 256>>>(lv, v, nrm, part, NV);
    reduce_kernel<<<BB, 256>>>(part, nrm, out);

    // 8) q_hat: softmax(lq) . q
    norm_kernel<<<BB, 256>>>(lq, nrm, NQ);
    wsum_kernel<<<dim3(8, BB), 256>>>(lq, q, nrm, part, NQ);
    reduce_kernel<<<BB, 256>>>(part, nrm, out + (long)BB * HH);
}

// round 11
// speedup vs baseline: 2.7908x; 1.5892x over previous
#include <cuda_runtime.h>
#include <cuda_fp16.h>
#include <cstdint>
#include <math.h>

#define BB  64
#define NV  2048
#define NQ  512
#define HH  256
#define HA  128

// ---------------- scratch (device globals) ---------------------------------
__device__ __half g_v16[(size_t)BB*NV*HH];
__device__ __half g_q16[(size_t)BB*NQ*HH];
__device__ __half g_WaT16[HH*HH];               // Waff^T (for qW = q @ Waff)
__device__ __half g_Wv16[HA*HH], g_Wq16[HA*HH];
__device__ __half g_qW16[(size_t)BB*NQ*HH];     // q @ Waff
__device__ float  g_qb[BB*NQ];                  // q . baff  (per-row scalar)
__device__ float  g_pv[(size_t)BB*NV*HA];
__device__ __half g_pvT16[(size_t)BB*HA*NV];
__device__ float  g_pq[(size_t)BB*NQ*HA];
__device__ __half g_pqT16[(size_t)BB*HA*NQ];
__device__ __half g_aff16[(size_t)BB*NQ*NV];
__device__ __half g_afT16[(size_t)BB*NV*NQ];
__device__ float  g_lv[BB*NV], g_lq[BB*NQ];
__device__ float2 g_normv[BB], g_normq[BB];
__device__ float  g_partv[BB*8*HH], g_partq[BB*8*HH];

#define TILE_B   10240               // 128 rows * 80B
#define BUF_B    (2 * TILE_B)        // A, B
#define DYNSMEM  (2 * BUF_B)         // 40960 (double buffer)
#define PLANE_B  33280               // 128*130*2 bounce plane (fits in DYNSMEM)

// ======================= low-level helpers =================================
__device__ __forceinline__ uint32_t smem_u32(const void* p) {
    uint32_t a;
    asm("{ .reg .u64 t; cvta.to.shared.u64 t, %1; cvt.u32.u64 %0, t; }"
        : "=r"(a) : "l"(p));
    return a;
}
__device__ __forceinline__ void ldsm4(uint32_t* r, uint32_t a) {
    asm volatile("ldmatrix.sync.aligned.m8n8.x4.shared.b16 {%0,%1,%2,%3}, [%4];"
                 : "=r"(r[0]), "=r"(r[1]), "=r"(r[2]), "=r"(r[3]) : "r"(a));
}
__device__ __forceinline__ void mma_f16(float* c, const uint32_t* a,
                                        const uint32_t* b) {
    asm volatile(
        "mma.sync.aligned.m16n8k16.row.col.f32.f16.f16.f32 "
        "{%0,%1,%2,%3}, {%4,%5,%6,%7}, {%8,%9}, {%0,%1,%2,%3};"
        : "+f"(c[0]), "+f"(c[1]), "+f"(c[2]), "+f"(c[3])
        : "r"(a[0]), "r"(a[1]), "r"(a[2]), "r"(a[3]), "r"(b[0]), "r"(b[1]));
}
__device__ __forceinline__ uint32_t cvt_h2(float x, float y) {
    uint32_t r;
    asm("cvt.rn.f16x2.f32 %0, %1, %2;" : "=r"(r) : "f"(y), "f"(x));
    return r;
}
__device__ __forceinline__ float tanh_fast(float x) {
    float e = __expf(2.0f * x);
    return 1.0f - __fdividef(2.0f, e + 1.0f);
}

// cp.async stage: 2 tiles (A, B), each 128 rows x 64B data -> 80B rows
__device__ __forceinline__ void stage_async(uint32_t buf,
        const __half* __restrict__ A, const __half* __restrict__ B,
        int lda, int ldb, int k0) {
    const int tid = threadIdx.x;
#pragma unroll
    for (int c = 0; c < 4; ++c) {
        const int lin = c * 256 + tid;
        const int sel = lin >> 9;
        const int li  = lin & 511;
        const int row = li >> 2, qt = li & 3;
        const __half* src = sel ? B : A;
        const int ld = sel ? ldb : lda;
        asm volatile("cp.async.cg.shared.global [%0], [%1], 16;"
            :: "r"(buf + sel * TILE_B + row * 80 + qt * 16),
               "l"((const char*)(src + (long)row * ld + k0) + qt * 16));
    }
}

// write a 128x128 fp16 smem plane (stride 130) to gmem, optional transpose
__device__ __forceinline__ void plane_out(const uint16_t* __restrict__ sm,
                                          __half* __restrict__ dst,
                                          long row0, long col0, long ld, int tr) {
    const int tid = threadIdx.x;
#pragma unroll
    for (int cI = 0; cI < 8; ++cI) {
        const int g = cI * 256 + tid;
        const int r = g >> 4, ch = g & 15;
        uint16_t e[8];
#pragma unroll
        for (int i = 0; i < 8; ++i)
            e[i] = tr ? sm[(ch * 8 + i) * 130 + r] : sm[r * 130 + ch * 8 + i];
        uint4 w;
        w.x = e[0] | ((uint32_t)e[1] << 16);
        w.y = e[2] | ((uint32_t)e[3] << 16);
        w.z = e[4] | ((uint32_t)e[5] << 16);
        w.w = e[6] | ((uint32_t)e[7] << 16);
        *(uint4*)(dst + (row0 + r) * ld + col0 + ch * 8) = w;
    }
}

// ============================================================================
// small conversion / prep kernels
// ============================================================================
__global__ __launch_bounds__(256)
void cvt_kernel(const float* __restrict__ x, __half* __restrict__ o, long n)
{
    const long i = ((long)blockIdx.x * 256 + threadIdx.x) * 4;
    if (i >= n) return;
    const float4 v = *(const float4*)(x + i);
    *(uint2*)((uint32_t*)o + (i >> 1)) =
        make_uint2(cvt_h2(v.x, v.y), cvt_h2(v.z, v.w));
}

__global__ __launch_bounds__(256)
void cvtT_kernel(const float* __restrict__ x, __half* __restrict__ o,
                 int R, int C)
{
    const int i = blockIdx.x * 256 + threadIdx.x;
    if (i >= R * C) return;
    const int r = i / C, c = i - r * C;
    o[(long)c * R + r] = __float2half(x[i]);
}

// qb[row] = q[row,:] . baff   (one warp per row)
__global__ __launch_bounds__(256)
void qb_kernel(const float* __restrict__ q, const float* __restrict__ baff,
               float* __restrict__ qb, int rows)
{
    const int w = (blockIdx.x * 256 + threadIdx.x) >> 5;
    const int lane = threadIdx.x & 31;
    if (w >= rows) return;
    const float* r = q + (long)w * HH;
    float s = 0.f;
#pragma unroll
    for (int k = 0; k < 8; ++k)
        s += r[lane + 32 * k] * baff[lane + 32 * k];
#pragma unroll
    for (int off = 16; off > 0; off >>= 1)
        s += __shfl_xor_sync(0xffffffffu, s, off);
    if (lane == 0) qb[w] = s;
}

// ============================================================================
// mma2: C[128-tile] = A @ B^T, fp16 operands, fp32 accumulate.
// 128x128x32 CTA tile, 8 warps (32x64), cp.async double buffer, 2 CTA/SM.
// MODE 0: C16 = f16(acc [+ bias])                            [qW]
// MODE 1: Cf = acc + bias (fp32); CT16 = transposed f16      [pv,pq]
// MODE 2: C16 = f16(tanh(acc + rowB[m])); CT16 transposed    [aff]
// MODE 3: logits[m] = Wh . tanh(PAdd[m] + acc[m]) + bh       [hidden]
// ============================================================================
template<int MODE>
__global__ __launch_bounds__(256, 2)
void mma2(const __half* __restrict__ A, const __half* __restrict__ B,
          const float* __restrict__ bias, const float* __restrict__ rowB,
          __half* __restrict__ C16, __half* __restrict__ CT16,
          float* __restrict__ Cf,
          const float* __restrict__ PAdd, const float* __restrict__ Wh,
          const float* __restrict__ bh, float* __restrict__ logits,
          int K, int lda, int ldb, int ldC, int ldCT, int rpb,
          long sA, long sB, long sOC, long sOCT, long sPAdd, int sLog)
{
    extern __shared__ __align__(16) unsigned char smem_[];
    __shared__ float sPart[2][128];

    const int z = blockIdx.z;
    A += z * sA;  B += z * sB;
    if (MODE == 2) { C16 += z * sOC; CT16 += z * sOCT; rowB += (long)z * NQ; }
    if (MODE == 3) { PAdd += z * sPAdd; logits += (long)z * sLog; }

    const long m0 = (long)(MODE == 3 ? blockIdx.x : blockIdx.y) * 128;
    const long n0 = (MODE == 3) ? 0 : (long)blockIdx.x * 128;
    A += m0 * lda;  B += n0 * ldb;

    const uint32_t sb0 = smem_u32(smem_);
    const int tid = threadIdx.x;
    const int l = tid & 31, wid = tid >> 5;
    const int wm = wid & 3, wn = wid >> 2;

    const int sub = l >> 3, lr = l & 7;
    const uint32_t aRow = wm * 32 + ((sub & 1) << 3) + lr;
    const uint32_t aK   = (uint32_t)((sub >> 1) << 3);
    const uint32_t bRow = ((sub & 2) << 2) + lr;
    const uint32_t bK   = (uint32_t)((sub & 1) << 3);

    float acc[2][8][4] = {};

    stage_async(sb0, A, B, lda, ldb, 0);
    asm volatile("cp.async.commit_group;" ::: "memory");

    const int nchunk = K >> 5;
    for (int ch = 0; ch < nchunk; ++ch) {
        if (ch + 1 < nchunk) {
            stage_async(sb0 + ((ch + 1) & 1) * BUF_B, A, B, lda, ldb,
                        (ch + 1) * 32);
            asm volatile("cp.async.commit_group;" ::: "memory");
            asm volatile("cp.async.wait_group 1;" ::: "memory");
        } else {
            asm volatile("cp.async.wait_group 0;" ::: "memory");
        }
        __syncthreads();

        const uint32_t cur = sb0 + (ch & 1) * BUF_B;
        const uint32_t sA = cur, sB = cur + TILE_B;

#pragma unroll
        for (int kt = 0; kt < 32; kt += 16) {
            uint32_t Af[2][4];
            const uint32_t ak = (kt + aK) * 2;
#pragma unroll
            for (int mt = 0; mt < 2; ++mt)
                ldsm4(Af[mt], sA + (aRow + mt * 16) * 80 + ak);
            const uint32_t bk = (kt + bK) * 2;
#pragma unroll
            for (int g = 0; g < 4; ++g) {
                uint32_t Bf[4];
                ldsm4(Bf, sB + (wn * 64 + g * 16 + bRow) * 80 + bk);
                mma_f16(acc[0][2*g],   Af[0], &Bf[0]);
                mma_f16(acc[0][2*g+1], Af[0], &Bf[2]);
                mma_f16(acc[1][2*g],   Af[1], &Bf[0]);
                mma_f16(acc[1][2*g+1], Af[1], &Bf[2]);
            }
        }
        __syncthreads();
    }

    // ---------------- epilogues ----------------
    if (MODE == 0) {
#pragma unroll
        for (int mt = 0; mt < 2; ++mt) {
            const long r0 = m0 + wm * 32 + mt * 16 + (l >> 2);
#pragma unroll
            for (int nt = 0; nt < 8; ++nt) {
                const long col = n0 + wn * 64 + nt * 8 + 2 * (l & 3);
                float2 b2 = bias ? *(const float2*)&bias[col]
                                 : make_float2(0.f, 0.f);
                ((uint32_t*)C16)[(r0 * (long)ldC + col) >> 1] =
                    cvt_h2(acc[mt][nt][0] + b2.x, acc[mt][nt][1] + b2.y);
                ((uint32_t*)C16)[((r0 + 8) * (long)ldC + col) >> 1] =
                    cvt_h2(acc[mt][nt][2] + b2.x, acc[mt][nt][3] + b2.y);
            }
        }
    } else if (MODE == 1 || MODE == 2) {
        uint32_t* pl = (uint32_t*)smem_;
#pragma unroll
        for (int mt = 0; mt < 2; ++mt) {
            const int rl = wm * 32 + mt * 16 + (l >> 2);
            float rb0 = 0.f, rb1 = 0.f;
            if (MODE == 2) {
                rb0 = rowB[m0 + rl];
                rb1 = rowB[m0 + rl + 8];
            }
#pragma unroll
            for (int nt = 0; nt < 8; ++nt) {
                const int c = wn * 64 + nt * 8 + 2 * (l & 3);
                float v0 = acc[mt][nt][0], v1 = acc[mt][nt][1];
                float v2 = acc[mt][nt][2], v3 = acc[mt][nt][3];
                if (MODE == 1) {
                    const float2 b2 = *(const float2*)&bias[n0 + c];
                    v0 += b2.x; v1 += b2.y; v2 += b2.x; v3 += b2.y;
                    const long r0 = m0 + rl;
                    *(float2*)&Cf[r0 * (long)ldC + n0 + c]       = make_float2(v0, v1);
                    *(float2*)&Cf[(r0 + 8) * (long)ldC + n0 + c] = make_float2(v2, v3);
                } else {
                    v0 = tanh_fast(v0 + rb0); v1 = tanh_fast(v1 + rb0);
                    v2 = tanh_fast(v2 + rb1); v3 = tanh_fast(v3 + rb1);
                }
                pl[(rl * 130 + c) >> 1]       = cvt_h2(v0, v1);
                pl[((rl + 8) * 130 + c) >> 1] = cvt_h2(v2, v3);
            }
        }
        __syncthreads();
        const uint16_t* sm = (const uint16_t*)smem_;
        if (MODE == 1) {
            const long b = m0 / rpb, nIn = m0 - b * rpb;
            plane_out(sm, CT16, b * HA, nIn, ldCT, 1);
        } else {
            plane_out(sm, C16,  m0, n0, ldC, 0);
            plane_out(sm, CT16, n0, m0, ldCT, 1);
        }
    } else {  // MODE 3
        float2 whr[8];
#pragma unroll
        for (int nt = 0; nt < 8; ++nt)
            whr[nt] = *(const float2*)&Wh[wn * 64 + nt * 8 + 2 * (l & 3)];
#pragma unroll
        for (int mt = 0; mt < 2; ++mt) {
            const int rr = wm * 32 + mt * 16 + (l >> 2);
            float s0 = 0.f, s1 = 0.f;
#pragma unroll
            for (int nt = 0; nt < 8; ++nt) {
                const int col = wn * 64 + nt * 8 + 2 * (l & 3);
                const float2 w = whr[nt];
                const float2 p0 = *(const float2*)&PAdd[(m0 + rr) * (long)HA + col];
                const float2 p1 = *(const float2*)&PAdd[(m0 + rr + 8) * (long)HA + col];
                s0 += w.x * tanh_fast(p0.x + acc[mt][nt][0])
                    + w.y * tanh_fast(p0.y + acc[mt][nt][1]);
                s1 += w.x * tanh_fast(p1.x + acc[mt][nt][2])
                    + w.y * tanh_fast(p1.y + acc[mt][nt][3]);
            }
            s0 += __shfl_xor_sync(0xffffffffu, s0, 1);
            s0 += __shfl_xor_sync(0xffffffffu, s0, 2);
            s1 += __shfl_xor_sync(0xffffffffu, s1, 1);
            s1 += __shfl_xor_sync(0xffffffffu, s1, 2);
            if ((l & 3) == 0) {
                sPart[wn][rr]     = s0;
                sPart[wn][rr + 8] = s1;
            }
        }
        __syncthreads();
        if (tid < 128)
            logits[m0 + tid] = sPart[0][tid] + sPart[1][tid] + bh[0];
    }
}

// ============================================================================
// Parallel softmax + weighted sum (3 stages)
// ============================================================================
__global__ __launch_bounds__(256)
void norm_kernel(const float* __restrict__ logits, float2* __restrict__ norm,
                 int N)
{
    const int b = blockIdx.x;
    logits += (long)b * N;
    __shared__ float sw[2048];
    __shared__ float red[256];
    const int tid = threadIdx.x;

    float mloc = -1e30f;
    for (int i = tid; i < N; i += 256) {
        float v = logits[i];
        sw[i] = v;
        mloc = fmaxf(mloc, v);
    }
    red[tid] = mloc;
    __syncthreads();
    for (int s = 128; s > 0; s >>= 1) {
        if (tid < s) red[tid] = fmaxf(red[tid], red[tid + s]);
        __syncthreads();
    }
    const float m = red[0];
    __syncthreads();

    float sloc = 0.f;
    for (int i = tid; i < N; i += 256)
        sloc += expf(sw[i] - m);
    red[tid] = sloc;
    __syncthreads();
    for (int s = 128; s > 0; s >>= 1) {
        if (tid < s) red[tid] += red[tid + s];
        __syncthreads();
    }
    if (tid == 0) norm[b] = make_float2(m, 1.f / red[0]);
}

__global__ __launch_bounds__(256)
void wsum_kernel(const float* __restrict__ logits, const float* __restrict__ X,
                 const float2* __restrict__ norm, float* __restrict__ part,
                 int N)
{
    const int b = blockIdx.y, c = blockIdx.x;
    const int CH = N >> 3;
    logits += (long)b * N + c * CH;
    X      += ((long)b * N + (long)c * CH) * HH;

    __shared__ float sw[256];
    const int tid = threadIdx.x;
    const float m = norm[b].x;
    for (int i = tid; i < CH; i += 256)
        sw[i] = expf(logits[i] - m);
    __syncthreads();

    float acc = 0.f;
#pragma unroll 4
    for (int n = 0; n < CH; ++n)
        acc = fmaf(sw[n], X[(long)n * HH + tid], acc);
    part[((b << 3) + c) * HH + tid] = acc;
}

__global__ __launch_bounds__(256)
void reduce_kernel(const float* __restrict__ part,
                   const float2* __restrict__ norm, float* __restrict__ out)
{
    const int b = blockIdx.x, tid = threadIdx.x;
    float s = 0.f;
#pragma unroll
    for (int c = 0; c < 8; ++c)
        s += part[((b << 3) + c) * HH + tid];
    out[(long)b * HH + tid] = s * norm[b].y;
}

// ============================================================================
extern "C" void kernel_launch(void* const* d_in, const int* in_sizes, int n_in,
                              void* d_out, int out_size)
{
    const float* v    = (const float*)d_in[0];
    const float* q    = (const float*)d_in[1];
    const float* Waff = (const float*)d_in[2];
    const float* baff = (const float*)d_in[3];
    const float* Wv   = (const float*)d_in[4];
    const float* bv   = (const float*)d_in[5];
    const float* Wq   = (const float*)d_in[6];
    const float* bq   = (const float*)d_in[7];
    const float* Whv  = (const float*)d_in[8];
    const float* bhv  = (const float*)d_in[9];
    const float* Whq  = (const float*)d_in[10];
    const float* bhq  = (const float*)d_in[11];
    float* out = (float*)d_out;

    __half *v16, *q16, *WaT16, *Wv16, *Wq16, *qW16, *pvT16, *pqT16, *aff16, *afT16;
    float *qb, *pv, *pq, *lv, *lq, *partv, *partq;
    float2 *nrmv, *nrmq;
    cudaGetSymbolAddress((void**)&v16,   g_v16);
    cudaGetSymbolAddress((void**)&q16,   g_q16);
    cudaGetSymbolAddress((void**)&WaT16, g_WaT16);
    cudaGetSymbolAddress((void**)&Wv16,  g_Wv16);
    cudaGetSymbolAddress((void**)&Wq16,  g_Wq16);
    cudaGetSymbolAddress((void**)&qW16,  g_qW16);
    cudaGetSymbolAddress((void**)&qb,    g_qb);
    cudaGetSymbolAddress((void**)&pv,    g_pv);
    cudaGetSymbolAddress((void**)&pvT16, g_pvT16);
    cudaGetSymbolAddress((void**)&pq,    g_pq);
    cudaGetSymbolAddress((void**)&pqT16, g_pqT16);
    cudaGetSymbolAddress((void**)&aff16, g_aff16);
    cudaGetSymbolAddress((void**)&afT16, g_afT16);
    cudaGetSymbolAddress((void**)&lv,    g_lv);
    cudaGetSymbolAddress((void**)&lq,    g_lq);
    cudaGetSymbolAddress((void**)&nrmv,  g_normv);
    cudaGetSymbolAddress((void**)&nrmq,  g_normq);
    cudaGetSymbolAddress((void**)&partv, g_partv);
    cudaGetSymbolAddress((void**)&partq, g_partq);

    cudaFuncSetAttribute(mma2<0>, cudaFuncAttributeMaxDynamicSharedMemorySize, DYNSMEM);
    cudaFuncSetAttribute(mma2<1>, cudaFuncAttributeMaxDynamicSharedMemorySize, DYNSMEM);
    cudaFuncSetAttribute(mma2<2>, cudaFuncAttributeMaxDynamicSharedMemorySize, DYNSMEM);
    cudaFuncSetAttribute(mma2<3>, cudaFuncAttributeMaxDynamicSharedMemorySize, DYNSMEM);

    // ---- fork streams off the capturing (default) stream ----
    cudaStream_t s1, s2, s3, s4;
    cudaStreamCreateWithFlags(&s1, cudaStreamNonBlocking);
    cudaStreamCreateWithFlags(&s2, cudaStreamNonBlocking);
    cudaStreamCreateWithFlags(&s3, cudaStreamNonBlocking);
    cudaStreamCreateWithFlags(&s4, cudaStreamNonBlocking);
    cudaEvent_t e0, eV, eQ, ePV, ePQ, eAFF, eO1, eO2;
    cudaEventCreateWithFlags(&e0,  cudaEventDisableTiming);
    cudaEventCreateWithFlags(&eV,  cudaEventDisableTiming);
    cudaEventCreateWithFlags(&eQ,  cudaEventDisableTiming);
    cudaEventCreateWithFlags(&ePV, cudaEventDisableTiming);
    cudaEventCreateWithFlags(&ePQ, cudaEventDisableTiming);
    cudaEventCreateWithFlags(&eAFF,cudaEventDisableTiming);
    cudaEventCreateWithFlags(&eO1, cudaEventDisableTiming);
    cudaEventCreateWithFlags(&eO2, cudaEventDisableTiming);

    cudaEventRecord(e0, 0);
    cudaStreamWaitEvent(s1, e0, 0);
    cudaStreamWaitEvent(s2, e0, 0);
    cudaStreamWaitEvent(s3, e0, 0);
    cudaStreamWaitEvent(s4, e0, 0);

    // default: cvt v (largest)
    cvt_kernel<<<(BB*NV*HH)/1024, 256, 0, 0>>>(v, v16, (long)BB*NV*HH);
    cudaEventRecord(eV, 0);

    // s1: cvt q
    cvt_kernel<<<(BB*NQ*HH)/1024, 256, 0, s1>>>(q, q16, (long)BB*NQ*HH);
    cudaEventRecord(eQ, s1);

    // s2: WaT + qb, then (after q16) qW, then (after v16) aff
    cvtT_kernel<<<(HH*HH)/256, 256, 0, s2>>>(Waff, WaT16, HH, HH);
    qb_kernel<<<(BB*NQ)/8, 256, 0, s2>>>(q, baff, qb, BB*NQ);
    cudaStreamWaitEvent(s2, eQ, 0);
    mma2<0><<<dim3(HH/128, (BB*NQ)/128, 1), 256, DYNSMEM, s2>>>(
        q16, WaT16, nullptr, nullptr, qW16, nullptr, nullptr,
        nullptr, nullptr, nullptr, nullptr,
        HH, HH, HH, HH, 0, 0, 0, 0, 0, 0, 0, 0);
    cudaStreamWaitEvent(s2, eV, 0);
    mma2<2><<<dim3(NV/128, NQ/128, BB), 256, DYNSMEM, s2>>>(
        qW16, v16, nullptr, qb, aff16, afT16, nullptr,
        nullptr, nullptr, nullptr, nullptr,
        HH, HH, HH, NV, NQ, 0,
        (long)NQ*HH, (long)NV*HH, (long)NQ*NV, (long)NV*NQ, 0, 0);
    cudaEventRecord(eAFF, s2);

    // s3: cvt Wv, then (after v16) pv
    cvt_kernel<<<(HA*HH)/1024, 256, 0, s3>>>(Wv, Wv16, HA*HH);
    cudaStreamWaitEvent(s3, eV, 0);
    mma2<1><<<dim3(1, (BB*NV)/128, 1), 256, DYNSMEM, s3>>>(
        v16, Wv16, bv, nullptr, nullptr, pvT16, pv,
        nullptr, nullptr, nullptr, nullptr,
        HH, HH, HH, HA, NV, NV, 0, 0, 0, 0, 0, 0);
    cudaEventRecord(ePV, s3);

    // s4: cvt Wq, then (after q16) pq
    cvt_kernel<<<(HA*HH)/1024, 256, 0, s4>>>(Wq, Wq16, HA*HH);
    cudaStreamWaitEvent(s4, eQ, 0);
    mma2<1><<<dim3(1, (BB*NQ)/128, 1), 256, DYNSMEM, s4>>>(
        q16, Wq16, bq, nullptr, nullptr, pqT16, pq,
        nullptr, nullptr, nullptr, nullptr,
        HH, HH, HH, HA, NQ, NQ, 0, 0, 0, 0, 0, 0);
    cudaEventRecord(ePQ, s4);

    // s3: G5 chain (logits_v -> softmax_v -> out[0..])
    cudaStreamWaitEvent(s3, eAFF, 0);
    cudaStreamWaitEvent(s3, ePQ, 0);
    mma2<3><<<dim3(NV/128, 1, BB), 256, DYNSMEM, s3>>>(
        afT16, pqT16, nullptr, nullptr, nullptr, nullptr, nullptr,
        pv, Whv, bhv, lv,
        NQ, NQ, NQ, 0, 0, 0,
        (long)NV*NQ, (long)HA*NQ, 0, 0, (long)NV*HA, NV);
    norm_kernel<<<BB, 256, 0, s3>>>(lv, nrmv, NV);
    wsum_kernel<<<dim3(8, BB), 256, 0, s3>>>(lv, v, nrmv, partv, NV);
    reduce_kernel<<<BB, 256, 0, s3>>>(partv, nrmv, out);
    cudaEventRecord(eO1, s3);

    // s4: G6 chain (logits_q -> softmax_q -> out[B*H..])
    cudaStreamWaitEvent(s4, eAFF, 0);
    cudaStreamWaitEvent(s4, ePV, 0);
    mma2<3><<<dim3(NQ/128, 1, BB), 256, DYNSMEM, s4>>>(
        aff16, pvT16, nullptr, nullptr, nullptr, nullptr, nullptr,
        pq, Whq, bhq, lq,
        NV, NV, NV, 0, 0, 0,
        (long)NQ*NV, (long)HA*NV, 0, 0, (long)NQ*HA, NQ);
    norm_kernel<<<BB, 256, 0, s4>>>(lq, nrmq, NQ);
    wsum_kernel<<<dim3(8, BB), 256, 0, s4>>>(lq, q, nrmq, partq, NQ);
    reduce_kernel<<<BB, 256, 0, s4>>>(partq, nrmq, out + (long)BB * HH);
    cudaEventRecord(eO2, s4);

    // join everything back into the capturing stream
    cudaStreamWaitEvent(0, eO1, 0);
    cudaStreamWaitEvent(0, eO2, 0);

    cudaStreamDestroy(s1); cudaStreamDestroy(s2);
    cudaStreamDestroy(s3); cudaStreamDestroy(s4);
    cudaEventDestroy(e0);  cudaEventDestroy(eV);  cudaEventDestroy(eQ);
    cudaEventDestroy(ePV); cudaEventDestroy(ePQ); cudaEventDestroy(eAFF);
    cudaEventDestroy(eO1); cudaEventDestroy(eO2);
}

// round 13
// speedup vs baseline: 2.8141x; 1.0083x over previous
#include <cuda_runtime.h>
#include <cuda_fp16.h>
#include <cstdint>
#include <math.h>

#define BB  64
#define NV  2048
#define NQ  512
#define HH  256
#define HA  128
#define BH  32          // batches per pipeline half

// ---------------- scratch (device globals) ---------------------------------
__device__ __half g_v16[(size_t)BB*NV*HH];
__device__ __half g_q16[(size_t)BB*NQ*HH];
__device__ __half g_WaT16[HH*HH];
__device__ __half g_Wv16[HA*HH], g_Wq16[HA*HH];
__device__ __half g_qW16[(size_t)BB*NQ*HH];
__device__ float  g_qb[BB*NQ];
__device__ __half g_pv16[(size_t)BB*NV*HA];
__device__ __half g_pvT16[(size_t)BB*HA*NV];
__device__ __half g_pq16[(size_t)BB*NQ*HA];
__device__ __half g_pqT16[(size_t)BB*HA*NQ];
__device__ __half g_aff16[(size_t)BB*NQ*NV];
__device__ __half g_afT16[(size_t)BB*NV*NQ];
__device__ float  g_lv[BB*NV], g_lq[BB*NQ];
__device__ float2 g_normv[BB], g_normq[BB];
__device__ float  g_partv[BB*8*HH], g_partq[BB*8*HH];

#define TILE_B   10240
#define BUF_B    (2 * TILE_B)
#define DYNSMEM  (2 * BUF_B)         // 40960
#define PLANE_B  33280

// ======================= low-level helpers =================================
__device__ __forceinline__ uint32_t smem_u32(const void* p) {
    uint32_t a;
    asm("{ .reg .u64 t; cvta.to.shared.u64 t, %1; cvt.u32.u64 %0, t; }"
        : "=r"(a) : "l"(p));
    return a;
}
__device__ __forceinline__ void ldsm4(uint32_t* r, uint32_t a) {
    asm volatile("ldmatrix.sync.aligned.m8n8.x4.shared.b16 {%0,%1,%2,%3}, [%4];"
                 : "=r"(r[0]), "=r"(r[1]), "=r"(r[2]), "=r"(r[3]) : "r"(a));
}
__device__ __forceinline__ void mma_f16(float* c, const uint32_t* a,
                                        const uint32_t* b) {
    asm volatile(
        "mma.sync.aligned.m16n8k16.row.col.f32.f16.f16.f32 "
        "{%0,%1,%2,%3}, {%4,%5,%6,%7}, {%8,%9}, {%0,%1,%2,%3};"
        : "+f"(c[0]), "+f"(c[1]), "+f"(c[2]), "+f"(c[3])
        : "r"(a[0]), "r"(a[1]), "r"(a[2]), "r"(a[3]), "r"(b[0]), "r"(b[1]));
}
__device__ __forceinline__ uint32_t cvt_h2(float x, float y) {
    uint32_t r;
    asm("cvt.rn.f16x2.f32 %0, %1, %2;" : "=r"(r) : "f"(y), "f"(x));
    return r;
}
__device__ __forceinline__ float tanh_fast(float x) {
    float e = __expf(2.0f * x);
    return 1.0f - __fdividef(2.0f, e + 1.0f);
}

__device__ __forceinline__ void stage_async(uint32_t buf,
        const __half* __restrict__ A, const __half* __restrict__ B,
        int lda, int ldb, int k0) {
    const int tid = threadIdx.x;
#pragma unroll
    for (int c = 0; c < 4; ++c) {
        const int lin = c * 256 + tid;
        const int sel = lin >> 9;
        const int li  = lin & 511;
        const int row = li >> 2, qt = li & 3;
        const __half* src = sel ? B : A;
        const int ld = sel ? ldb : lda;
        asm volatile("cp.async.cg.shared.global [%0], [%1], 16;"
            :: "r"(buf + sel * TILE_B + row * 80 + qt * 16),
               "l"((const char*)(src + (long)row * ld + k0) + qt * 16));
    }
}

__device__ __forceinline__ void plane_out(const uint16_t* __restrict__ sm,
                                          __half* __restrict__ dst,
                                          long row0, long col0, long ld, int tr) {
    const int tid = threadIdx.x;
#pragma unroll
    for (int cI = 0; cI < 8; ++cI) {
        const int g = cI * 256 + tid;
        const int r = g >> 4, ch = g & 15;
        uint16_t e[8];
#pragma unroll
        for (int i = 0; i < 8; ++i)
            e[i] = tr ? sm[(ch * 8 + i) * 130 + r] : sm[r * 130 + ch * 8 + i];
        uint4 w;
        w.x = e[0] | ((uint32_t)e[1] << 16);
        w.y = e[2] | ((uint32_t)e[3] << 16);
        w.z = e[4] | ((uint32_t)e[5] << 16);
        w.w = e[6] | ((uint32_t)e[7] << 16);
        *(uint4*)(dst + (row0 + r) * ld + col0 + ch * 8) = w;
    }
}

// ============================================================================
// prep kernels
// ============================================================================
__global__ __launch_bounds__(256)
void cvt_kernel(const float* __restrict__ x, __half* __restrict__ o, long n)
{
    const long i = ((long)blockIdx.x * 256 + threadIdx.x) * 4;
    if (i >= n) return;
    const float4 v = *(const float4*)(x + i);
    *(uint2*)((uint32_t*)o + (i >> 1)) =
        make_uint2(cvt_h2(v.x, v.y), cvt_h2(v.z, v.w));
}

__global__ __launch_bounds__(256)
void cvtT_kernel(const float* __restrict__ x, __half* __restrict__ o,
                 int R, int C)
{
    const int i = blockIdx.x * 256 + threadIdx.x;
    if (i >= R * C) return;
    const int r = i / C, c = i - r * C;
    o[(long)c * R + r] = __float2half(x[i]);
}

__global__ __launch_bounds__(256)
void qb_kernel(const float* __restrict__ q, const float* __restrict__ baff,
               float* __restrict__ qb, int rows)
{
    const int w = (blockIdx.x * 256 + threadIdx.x) >> 5;
    const int lane = threadIdx.x & 31;
    if (w >= rows) return;
    const float* r = q + (long)w * HH;
    float s = 0.f;
#pragma unroll
    for (int k = 0; k < 8; ++k)
        s += r[lane + 32 * k] * baff[lane + 32 * k];
#pragma unroll
    for (int off = 16; off > 0; off >>= 1)
        s += __shfl_xor_sync(0xffffffffu, s, off);
    if (lane == 0) qb[w] = s;
}

// ============================================================================
// mma2: C = A @ B^T (fp16 in, fp32 acc), 128x128x32 tile, 8 warps, 2 CTA/SM.
// MODE 0: C16 = f16(acc [+bias]) direct                      [qW]
// MODE 1: C16 = f16(acc + bias) + CT16 transposed (planes)   [pv,pq]
// MODE 2: C16 = f16(tanh(acc + rowB)) + CT16 transposed      [aff]
// MODE 3: logits[m] = Wh . tanh(f32(PAdd16[m]) + acc[m]) + bh
// ============================================================================
template<int MODE>
__global__ __launch_bounds__(256, 2)
void mma2(const __half* __restrict__ A, const __half* __restrict__ B,
          const float* __restrict__ bias, const float* __restrict__ rowB,
          __half* __restrict__ C16, __half* __restrict__ CT16,
          const __half* __restrict__ PAdd16,
          const float* __restrict__ Wh, const float* __restrict__ bh,
          float* __restrict__ logits,
          int K, int lda, int ldb, int ldC, int ldCT, int rpb,
          long sA, long sB, long sOC, long sOCT, long sPAdd, int sLog)
{
    extern __shared__ __align__(16) unsigned char smem_[];
    __shared__ float sPart[2][128];

    const int z = blockIdx.z;
    A += z * sA;  B += z * sB;
    if (MODE == 2) { C16 += z * sOC; CT16 += z * sOCT; rowB += (long)z * NQ; }
    if (MODE == 3) { PAdd16 += z * sPAdd; logits += (long)z * sLog; }

    const long m0 = (long)(MODE == 3 ? blockIdx.x : blockIdx.y) * 128;
    const long n0 = (MODE == 3) ? 0 : (long)blockIdx.x * 128;
    A += m0 * lda;  B += n0 * ldb;

    const uint32_t sb0 = smem_u32(smem_);
    const int tid = threadIdx.x;
    const int l = tid & 31, wid = tid >> 5;
    const int wm = wid & 3, wn = wid >> 2;

    const int sub = l >> 3, lr = l & 7;
    const uint32_t aRow = wm * 32 + ((sub & 1) << 3) + lr;
    const uint32_t aK   = (uint32_t)((sub >> 1) << 3);
    const uint32_t bRow = ((sub & 2) << 2) + lr;
    const uint32_t bK   = (uint32_t)((sub & 1) << 3);

    float acc[2][8][4] = {};

    stage_async(sb0, A, B, lda, ldb, 0);
    asm volatile("cp.async.commit_group;" ::: "memory");

    const int nchunk = K >> 5;
    for (int ch = 0; ch < nchunk; ++ch) {
        if (ch + 1 < nchunk) {
            stage_async(sb0 + ((ch + 1) & 1) * BUF_B, A, B, lda, ldb,
                        (ch + 1) * 32);
            asm volatile("cp.async.commit_group;" ::: "memory");
            asm volatile("cp.async.wait_group 1;" ::: "memory");
        } else {
            asm volatile("cp.async.wait_group 0;" ::: "memory");
        }
        __syncthreads();

        const uint32_t cur = sb0 + (ch & 1) * BUF_B;
        const uint32_t sA = cur, sB = cur + TILE_B;

#pragma unroll
        for (int kt = 0; kt < 32; kt += 16) {
            uint32_t Af[2][4];
            const uint32_t ak = (kt + aK) * 2;
#pragma unroll
            for (int mt = 0; mt < 2; ++mt)
                ldsm4(Af[mt], sA + (aRow + mt * 16) * 80 + ak);
            const uint32_t bk = (kt + bK) * 2;
#pragma unroll
            for (int g = 0; g < 4; ++g) {
                uint32_t Bf[4];
                ldsm4(Bf, sB + (wn * 64 + g * 16 + bRow) * 80 + bk);
                mma_f16(acc[0][2*g],   Af[0], &Bf[0]);
                mma_f16(acc[0][2*g+1], Af[0], &Bf[2]);
                mma_f16(acc[1][2*g],   Af[1], &Bf[0]);
                mma_f16(acc[1][2*g+1], Af[1], &Bf[2]);
            }
        }
        __syncthreads();
    }

    // ---------------- epilogues ----------------
    if (MODE == 0) {
#pragma unroll
        for (int mt = 0; mt < 2; ++mt) {
            const long r0 = m0 + wm * 32 + mt * 16 + (l >> 2);
#pragma unroll
            for (int nt = 0; nt < 8; ++nt) {
                const long col = n0 + wn * 64 + nt * 8 + 2 * (l & 3);
                float2 b2 = bias ? *(const float2*)&bias[col]
                                 : make_float2(0.f, 0.f);
                ((uint32_t*)C16)[(r0 * (long)ldC + col) >> 1] =
                    cvt_h2(acc[mt][nt][0] + b2.x, acc[mt][nt][1] + b2.y);
                ((uint32_t*)C16)[((r0 + 8) * (long)ldC + col) >> 1] =
                    cvt_h2(acc[mt][nt][2] + b2.x, acc[mt][nt][3] + b2.y);
            }
        }
    } else if (MODE == 1 || MODE == 2) {
        uint32_t* pl = (uint32_t*)smem_;
#pragma unroll
        for (int mt = 0; mt < 2; ++mt) {
            const int rl = wm * 32 + mt * 16 + (l >> 2);
            float rb0 = 0.f, rb1 = 0.f;
            if (MODE == 2) {
                rb0 = rowB[m0 + rl];
                rb1 = rowB[m0 + rl + 8];
            }
#pragma unroll
            for (int nt = 0; nt < 8; ++nt) {
                const int c = wn * 64 + nt * 8 + 2 * (l & 3);
                float v0 = acc[mt][nt][0], v1 = acc[mt][nt][1];
                float v2 = acc[mt][nt][2], v3 = acc[mt][nt][3];
                if (MODE == 1) {
                    const float2 b2 = *(const float2*)&bias[n0 + c];
                    v0 += b2.x; v1 += b2.y; v2 += b2.x; v3 += b2.y;
                } else {
                    v0 = tanh_fast(v0 + rb0); v1 = tanh_fast(v1 + rb0);
                    v2 = tanh_fast(v2 + rb1); v3 = tanh_fast(v3 + rb1);
                }
                pl[(rl * 130 + c) >> 1]       = cvt_h2(v0, v1);
                pl[((rl + 8) * 130 + c) >> 1] = cvt_h2(v2, v3);
            }
        }
        __syncthreads();
        const uint16_t* sm = (const uint16_t*)smem_;
        if (MODE == 1) {
            const long b = m0 / rpb, nIn = m0 - b * rpb;
            plane_out(sm, C16,  m0, 0, ldC, 0);
            plane_out(sm, CT16, b * HA, nIn, ldCT, 1);
        } else {
            plane_out(sm, C16,  m0, n0, ldC, 0);
            plane_out(sm, CT16, n0, m0, ldCT, 1);
        }
    } else {  // MODE 3
        float2 whr[8];
#pragma unroll
        for (int nt = 0; nt < 8; ++nt)
            whr[nt] = *(const float2*)&Wh[wn * 64 + nt * 8 + 2 * (l & 3)];
#pragma unroll
        for (int mt = 0; mt < 2; ++mt) {
            const int rr = wm * 32 + mt * 16 + (l >> 2);
            float s0 = 0.f, s1 = 0.f;
#pragma unroll
            for (int nt = 0; nt < 8; ++nt) {
                const int col = wn * 64 + nt * 8 + 2 * (l & 3);
                const float2 w = whr[nt];
                const float2 p0 = __half22float2(
                    *(const __half2*)&PAdd16[(m0 + rr) * (long)HA + col]);
                const float2 p1 = __half22float2(
                    *(const __half2*)&PAdd16[(m0 + rr + 8) * (long)HA + col]);
                s0 += w.x * tanh_fast(p0.x + acc[mt][nt][0])
                    + w.y * tanh_fast(p0.y + acc[mt][nt][1]);
                s1 += w.x * tanh_fast(p1.x + acc[mt][nt][2])
                    + w.y * tanh_fast(p1.y + acc[mt][nt][3]);
            }
            s0 += __shfl_xor_sync(0xffffffffu, s0, 1);
            s0 += __shfl_xor_sync(0xffffffffu, s0, 2);
            s1 += __shfl_xor_sync(0xffffffffu, s1, 1);
            s1 += __shfl_xor_sync(0xffffffffu, s1, 2);
            if ((l & 3) == 0) {
                sPart[wn][rr]     = s0;
                sPart[wn][rr + 8] = s1;
            }
        }
        __syncthreads();
        if (tid < 128)
            logits[m0 + tid] = sPart[0][tid] + sPart[1][tid] + bh[0];
    }
}

// ============================================================================
// Parallel softmax + weighted sum
// ============================================================================
__global__ __launch_bounds__(256)
void norm_kernel(const float* __restrict__ logits, float2* __restrict__ norm,
                 int N)
{
    const int b = blockIdx.x;
    logits += (long)b * N;
    __shared__ float sw[2048];
    __shared__ float red[256];
    const int tid = threadIdx.x;

    float mloc = -1e30f;
    for (int i = tid; i < N; i += 256) {
        float v = logits[i];
        sw[i] = v;
        mloc = fmaxf(mloc, v);
    }
    red[tid] = mloc;
    __syncthreads();
    for (int s = 128; s > 0; s >>= 1) {
        if (tid < s) red[tid] = fmaxf(red[tid], red[tid + s]);
        __syncthreads();
    }
    const float m = red[0];
    __syncthreads();

    float sloc = 0.f;
    for (int i = tid; i < N; i += 256)
        sloc += expf(sw[i] - m);
    red[tid] = sloc;
    __syncthreads();
    for (int s = 128; s > 0; s >>= 1) {
        if (tid < s) red[tid] += red[tid + s];
        __syncthreads();
    }
    if (tid == 0) norm[b] = make_float2(m, 1.f / red[0]);
}

__global__ __launch_bounds__(256)
void wsum_kernel(const float* __restrict__ logits, const float* __restrict__ X,
                 const float2* __restrict__ norm, float* __restrict__ part,
                 int N)
{
    const int b = blockIdx.y, c = blockIdx.x;
    const int CH = N >> 3;
    logits += (long)b * N + c * CH;
    X      += ((long)b * N + (long)c * CH) * HH;

    __shared__ float sw[256];
    const int tid = threadIdx.x;
    const float m = norm[b].x;
    for (int i = tid; i < CH; i += 256)
        sw[i] = expf(logits[i] - m);
    __syncthreads();

    float acc = 0.f;
#pragma unroll 4
    for (int n = 0; n < CH; ++n)
        acc = fmaf(sw[n], X[(long)n * HH + tid], acc);
    part[((b << 3) + c) * HH + tid] = acc;
}

__global__ __launch_bounds__(256)
void reduce_kernel(const float* __restrict__ part,
                   const float2* __restrict__ norm, float* __restrict__ out)
{
    const int b = blockIdx.x, tid = threadIdx.x;
    float s = 0.f;
#pragma unroll
    for (int c = 0; c < 8; ++c)
        s += part[((b << 3) + c) * HH + tid];
    out[(long)b * HH + tid] = s * norm[b].y;
}

// ============================================================================
extern "C" void kernel_launch(void* const* d_in, const int* in_sizes, int n_in,
                              void* d_out, int out_size)
{
    const float* v    = (const float*)d_in[0];
    const float* q    = (const float*)d_in[1];
    const float* Waff = (const float*)d_in[2];
    const float* baff = (const float*)d_in[3];
    const float* Wv   = (const float*)d_in[4];
    const float* bv   = (const float*)d_in[5];
    const float* Wq   = (const float*)d_in[6];
    const float* bq   = (const float*)d_in[7];
    const float* Whv  = (const float*)d_in[8];
    const float* bhv  = (const float*)d_in[9];
    const float* Whq  = (const float*)d_in[10];
    const float* bhq  = (const float*)d_in[11];
    float* out = (float*)d_out;

    __half *v16, *q16, *WaT16, *Wv16, *Wq16, *qW16, *pv16, *pvT16, *pq16,
           *pqT16, *aff16, *afT16;
    float *qb, *lv, *lq, *partv, *partq;
    float2 *nrmv, *nrmq;
    cudaGetSymbolAddress((void**)&v16,   g_v16);
    cudaGetSymbolAddress((void**)&q16,   g_q16);
    cudaGetSymbolAddress((void**)&WaT16, g_WaT16);
    cudaGetSymbolAddress((void**)&Wv16,  g_Wv16);
    cudaGetSymbolAddress((void**)&Wq16,  g_Wq16);
    cudaGetSymbolAddress((void**)&qW16,  g_qW16);
    cudaGetSymbolAddress((void**)&qb,    g_qb);
    cudaGetSymbolAddress((void**)&pv16,  g_pv16);
    cudaGetSymbolAddress((void**)&pvT16, g_pvT16);
    cudaGetSymbolAddress((void**)&pq16,  g_pq16);
    cudaGetSymbolAddress((void**)&pqT16, g_pqT16);
    cudaGetSymbolAddress((void**)&aff16, g_aff16);
    cudaGetSymbolAddress((void**)&afT16, g_afT16);
    cudaGetSymbolAddress((void**)&lv,    g_lv);
    cudaGetSymbolAddress((void**)&lq,    g_lq);
    cudaGetSymbolAddress((void**)&nrmv,  g_normv);
    cudaGetSymbolAddress((void**)&nrmq,  g_normq);
    cudaGetSymbolAddress((void**)&partv, g_partv);
    cudaGetSymbolAddress((void**)&partq, g_partq);

    cudaFuncSetAttribute(mma2<0>, cudaFuncAttributeMaxDynamicSharedMemorySize, DYNSMEM);
    cudaFuncSetAttribute(mma2<1>, cudaFuncAttributeMaxDynamicSharedMemorySize, DYNSMEM);
    cudaFuncSetAttribute(mma2<2>, cudaFuncAttributeMaxDynamicSharedMemorySize, DYNSMEM);
    cudaFuncSetAttribute(mma2<3>, cudaFuncAttributeMaxDynamicSharedMemorySize, DYNSMEM);

    // ---- 4 streams total (proven safe), 2 per pipeline half ----
    cudaStream_t sA[2], sB[2];
    cudaEvent_t eW, eV[2], ePV[2], eAFF[2], eOv[2], eOq[2];
    for (int h = 0; h < 2; ++h) {
        cudaStreamCreateWithFlags(&sA[h], cudaStreamNonBlocking);
        cudaStreamCreateWithFlags(&sB[h], cudaStreamNonBlocking);
        cudaEventCreateWithFlags(&eV[h],   cudaEventDisableTiming);
        cudaEventCreateWithFlags(&ePV[h],  cudaEventDisableTiming);
        cudaEventCreateWithFlags(&eAFF[h], cudaEventDisableTiming);
        cudaEventCreateWithFlags(&eOv[h],  cudaEventDisableTiming);
        cudaEventCreateWithFlags(&eOq[h],  cudaEventDisableTiming);
    }
    cudaEventCreateWithFlags(&eW, cudaEventDisableTiming);

    // weight preps on the capturing (default) stream
    cvtT_kernel<<<(HH*HH)/256, 256>>>(Waff, WaT16, HH, HH);
    cvt_kernel<<<(HA*HH)/1024, 256>>>(Wv, Wv16, HA*HH);
    cvt_kernel<<<(HA*HH)/1024, 256>>>(Wq, Wq16, HA*HH);
    cudaEventRecord(eW, 0);

    for (int h = 0; h < 2; ++h) {
        const long z0 = (long)h * BH;
        const long oVH = z0 * NV * HH, oQH = z0 * NQ * HH;
        const long oPV = z0 * NV * HA, oPVT = z0 * HA * NV;
        const long oPQ = z0 * NQ * HA, oPQT = z0 * HA * NQ;
        const long oAF = z0 * NQ * NV, oAFT = z0 * NV * NQ;
        const long oLV = z0 * NV, oLQ = z0 * NQ;

        // sA: cvt_v -> pv(+pvT) -> [aff] -> G5 chain
        cudaStreamWaitEvent(sA[h], eW, 0);
        cvt_kernel<<<(BH*NV*HH)/1024, 256, 0, sA[h]>>>(
            v + oVH, v16 + oVH, (long)BH*NV*HH);
        cudaEventRecord(eV[h], sA[h]);
        mma2<1><<<dim3(1, BH*NV/128, 1), 256, DYNSMEM, sA[h]>>>(
            v16 + oVH, Wv16, bv, nullptr, pv16 + oPV, pvT16 + oPVT, nullptr,
            nullptr, nullptr, nullptr,
            HH, HH, HH, HA, NV, NV, 0, 0, 0, 0, 0, 0);
        cudaEventRecord(ePV[h], sA[h]);

        // sB: cvt_q -> qb -> qW -> pq(+pqT) -> [v16] aff -> [pv] G6 chain
        cudaStreamWaitEvent(sB[h], eW, 0);
        cvt_kernel<<<(BH*NQ*HH)/1024, 256, 0, sB[h]>>>(
            q + oQH, q16 + oQH, (long)BH*NQ*HH);
        qb_kernel<<<(BH*NQ)/8, 256, 0, sB[h]>>>(
            q + oQH, baff, qb + oLQ, BH*NQ);
        mma2<0><<<dim3(HH/128, BH*NQ/128, 1), 256, DYNSMEM, sB[h]>>>(
            q16 + oQH, WaT16, nullptr, nullptr, qW16 + oQH, nullptr, nullptr,
            nullptr, nullptr, nullptr,
            HH, HH, HH, HH, 0, 0, 0, 0, 0, 0, 0, 0);
        mma2<1><<<dim3(1, BH*NQ/128, 1), 256, DYNSMEM, sB[h]>>>(
            q16 + oQH, Wq16, bq, nullptr, pq16 + oPQ, pqT16 + oPQT, nullptr,
            nullptr, nullptr, nullptr,
            HH, HH, HH, HA, NQ, NQ, 0, 0, 0, 0, 0, 0);
        cudaStreamWaitEvent(sB[h], eV[h], 0);
        mma2<2><<<dim3(NV/128, NQ/128, BH), 256, DYNSMEM, sB[h]>>>(
            qW16 + oQH, v16 + oVH, nullptr, qb + oLQ,
            aff16 + oAF, afT16 + oAFT, nullptr, nullptr, nullptr, nullptr,
            HH, HH, HH, NV, NQ, 0,
            (long)NQ*HH, (long)NV*HH, (long)NQ*NV, (long)NV*NQ, 0, 0);
        cudaEventRecord(eAFF[h], sB[h]);

        // sA: G5 chain (aff event implies pq/pqT done; pv in-stream)
        cudaStreamWaitEvent(sA[h], eAFF[h], 0);
        mma2<3><<<dim3(NV/128, 1, BH), 256, DYNSMEM, sA[h]>>>(
            afT16 + oAFT, pqT16 + oPQT, nullptr, nullptr, nullptr, nullptr,
            pv16 + oPV, Whv, bhv, lv + oLV,
            NQ, NQ, NQ, 0, 0, 0,
            (long)NV*NQ, (long)HA*NQ, 0, 0, (long)NV*HA, NV);
        norm_kernel<<<BH, 256, 0, sA[h]>>>(lv + oLV, nrmv + z0, NV);
        wsum_kernel<<<dim3(8, BH), 256, 0, sA[h]>>>(
            lv + oLV, v + oVH, nrmv + z0, partv + z0*8*HH, NV);
        reduce_kernel<<<BH, 256, 0, sA[h]>>>(
            partv + z0*8*HH, nrmv + z0, out + z0*HH);
        cudaEventRecord(eOv[h], sA[h]);

        // sB: G6 chain (aff in-stream; needs pvT cross-stream)
        cudaStreamWaitEvent(sB[h], ePV[h], 0);
        mma2<3><<<dim3(NQ/128, 1, BH), 256, DYNSMEM, sB[h]>>>(
            aff16 + oAF, pvT16 + oPVT, nullptr, nullptr, nullptr, nullptr,
            pq16 + oPQ, Whq, bhq, lq + oLQ,
            NV, NV, NV, 0, 0, 0,
            (long)NQ*NV, (long)HA*NV, 0, 0, (long)NQ*HA, NQ);
        norm_kernel<<<BH, 256, 0, sB[h]>>>(lq + oLQ, nrmq + z0, NQ);
        wsum_kernel<<<dim3(8, BH), 256, 0, sB[h]>>>(
            lq + oLQ, q + oQH, nrmq + z0, partq + z0*8*HH, NQ);
        reduce_kernel<<<BH, 256, 0, sB[h]>>>(
            partq + z0*8*HH, nrmq + z0, out + (long)BB*HH + z0*HH);
        cudaEventRecord(eOq[h], sB[h]);
    }

    for (int h = 0; h < 2; ++h) {
        cudaStreamWaitEvent(0, eOv[h], 0);
        cudaStreamWaitEvent(0, eOq[h], 0);
    }

    for (int h = 0; h < 2; ++h) {
        cudaStreamDestroy(sA[h]); cudaStreamDestroy(sB[h]);
        cudaEventDestroy(eV[h]);  cudaEventDestroy(ePV[h]);
        cudaEventDestroy(eAFF[h]);
        cudaEventDestroy(eOv[h]); cudaEventDestroy(eOq[h]);
    }
    cudaEventDestroy(eW);
}